// round 4
// baseline (speedup 1.0000x reference)
#include <cuda_runtime.h>

// Problem constants (B=1)
#define TSEQ   4096
#define CDIM   768
#define NHEAD  12
#define DHEAD  64
#define QKVN   2304   // 3*C

// Scratch (allocation-free rule: __device__ globals)
__device__ float g_qkv[TSEQ * QKVN];   // [T, 3C]  (q | k | v)
__device__ float g_y[TSEQ * CDIM];     // [T, C]   attention output

// ----------------------------------------------------------------------------
// SGEMM with bias:  C[M,N] = A[M,K] @ B[K,N] + bias[N]
// BM=BN=128, BK=8, 256 threads, 8x8 register microtile.
// MODE 0: A = param (x),  C = g_qkv
// MODE 1: A = g_y,        C = param (d_out)
// ----------------------------------------------------------------------------
#define GBM 128
#define GBN 128
#define GBK 8
#define GTM 8
#define GTN 8

template <int MODE>
__global__ __launch_bounds__(256, 2)
void sgemm_bias(const float* __restrict__ Ain, const float* __restrict__ B,
                const float* __restrict__ bias, float* __restrict__ Cout,
                int M, int N, int K)
{
    const float* A = (MODE == 0) ? Ain : g_y;
    float*       C = (MODE == 0) ? g_qkv : Cout;

    __shared__ float As[GBK][GBM];   // k-major (transposed)
    __shared__ float Bs[GBK][GBN];

    const int tid  = threadIdx.x;
    const int brow = blockIdx.y * GBM;
    const int bcol = blockIdx.x * GBN;
    const int trow = (tid >> 4) * GTM;       // 16 row-groups
    const int tcol = (tid & 15) * GTN;       // 16 col-groups

    const int a_row = tid >> 1;              // 0..127
    const int a_k   = (tid & 1) * 4;         // 0 or 4
    const int b_row = tid >> 5;              // 0..7
    const int b_col = (tid & 31) * 4;        // 0..124

    float acc[GTM][GTN];
#pragma unroll
    for (int i = 0; i < GTM; i++)
#pragma unroll
        for (int j = 0; j < GTN; j++) acc[i][j] = 0.0f;

    const float* Aptr = A + (size_t)(brow + a_row) * K + a_k;
    const float* Bptr = B + (size_t)b_row * N + bcol + b_col;

    for (int k0 = 0; k0 < K; k0 += GBK) {
        const float4 av = *reinterpret_cast<const float4*>(Aptr + k0);
        const float4 bv = *reinterpret_cast<const float4*>(Bptr + (size_t)k0 * N);
        As[a_k + 0][a_row] = av.x;
        As[a_k + 1][a_row] = av.y;
        As[a_k + 2][a_row] = av.z;
        As[a_k + 3][a_row] = av.w;
        *reinterpret_cast<float4*>(&Bs[b_row][b_col]) = bv;
        __syncthreads();

#pragma unroll
        for (int kk = 0; kk < GBK; kk++) {
            const float4 a0 = *reinterpret_cast<const float4*>(&As[kk][trow]);
            const float4 a1 = *reinterpret_cast<const float4*>(&As[kk][trow + 4]);
            const float4 b0 = *reinterpret_cast<const float4*>(&Bs[kk][tcol]);
            const float4 b1 = *reinterpret_cast<const float4*>(&Bs[kk][tcol + 4]);
            const float ar[8] = {a0.x, a0.y, a0.z, a0.w, a1.x, a1.y, a1.z, a1.w};
            const float br[8] = {b0.x, b0.y, b0.z, b0.w, b1.x, b1.y, b1.z, b1.w};
#pragma unroll
            for (int i = 0; i < GTM; i++)
#pragma unroll
                for (int j = 0; j < GTN; j++)
                    acc[i][j] = fmaf(ar[i], br[j], acc[i][j]);
        }
        __syncthreads();
    }

#pragma unroll
    for (int i = 0; i < GTM; i++) {
        float* crow = C + (size_t)(brow + trow + i) * N + bcol + tcol;
#pragma unroll
        for (int j = 0; j < GTN; j += 4) {
            float4 o;
            o.x = acc[i][j + 0] + bias[bcol + tcol + j + 0];
            o.y = acc[i][j + 1] + bias[bcol + tcol + j + 1];
            o.z = acc[i][j + 2] + bias[bcol + tcol + j + 2];
            o.w = acc[i][j + 3] + bias[bcol + tcol + j + 3];
            *reinterpret_cast<float4*>(crow + j) = o;
        }
    }
}

// ----------------------------------------------------------------------------
// Causal flash attention, fp32.
// Block = one (head, 64-row query tile); 256 threads as 16x16; 4x4 fragments.
// S-fragment columns are STRIDED (j = tx + 16c) so K-row LDS.128 reads with
// pad-68 rows are bank-conflict-free. O-fragment d-columns are contiguous
// (d = 4*tx), P stored row-major, PV in dot-product form -> conflict-free.
// ----------------------------------------------------------------------------
#define PADK 68     // floats per smem row (17 float4s: keeps 16B alignment,
                    // 68 % 32 == 4 gives conflict-free strided row access)

__global__ __launch_bounds__(256)
void flash_attn()
{
    extern __shared__ float sm[];
    float* Qs = sm;                  // [64][PADK] rows i, cols d
    float* Ks = Qs + 64 * PADK;      // [64][PADK] rows j, cols d
    float* Vs = Ks + 64 * PADK;      // [64][PADK] rows j, cols d
    float* Ps = Vs + 64 * PADK;      // [64][PADK] rows i, cols j

    const int h     = blockIdx.y;
    const int qtile = gridDim.x - 1 - blockIdx.x;   // big tiles first
    const int q0    = qtile * 64;
    const int tid   = threadIdx.x;
    const int tx    = tid & 15;
    const int ty    = tid >> 4;
    const int i0    = ty << 2;   // 4 query rows
    const int d0    = tx << 2;   // 4 output d-cols

    // Load Q tile
    for (int idx = tid; idx < 64 * 16; idx += 256) {
        const int i  = idx >> 4;
        const int d4 = (idx & 15) << 2;
        const float4 v = *reinterpret_cast<const float4*>(
            &g_qkv[(size_t)(q0 + i) * QKVN + h * DHEAD + d4]);
        *reinterpret_cast<float4*>(&Qs[i * PADK + d4]) = v;
    }

    float m_r[4], l_r[4], O_r[4][4];
#pragma unroll
    for (int r = 0; r < 4; r++) {
        m_r[r] = -1e30f;
        l_r[r] = 0.0f;
#pragma unroll
        for (int c = 0; c < 4; c++) O_r[r][c] = 0.0f;
    }

    const float scale = 0.125f;   // 1/sqrt(64)

    for (int kt = 0; kt <= qtile; kt++) {
        const int k0 = kt * 64;
        __syncthreads();          // previous PV done reading Vs/Ps
        // Load K, V tiles
        for (int idx = tid; idx < 64 * 16; idx += 256) {
            const int j  = idx >> 4;
            const int d4 = (idx & 15) << 2;
            const float* bp = &g_qkv[(size_t)(k0 + j) * QKVN + h * DHEAD + d4];
            *reinterpret_cast<float4*>(&Ks[j * PADK + d4]) =
                *reinterpret_cast<const float4*>(bp + CDIM);
            *reinterpret_cast<float4*>(&Vs[j * PADK + d4]) =
                *reinterpret_cast<const float4*>(bp + 2 * CDIM);
        }
        __syncthreads();

        // S = Q K^T (thread cols j = tx + 16c)
        float S[4][4];
#pragma unroll
        for (int r = 0; r < 4; r++)
#pragma unroll
            for (int c = 0; c < 4; c++) S[r][c] = 0.0f;

#pragma unroll
        for (int d4 = 0; d4 < 64; d4 += 4) {
            float4 qf[4], kf[4];
#pragma unroll
            for (int r = 0; r < 4; r++)
                qf[r] = *reinterpret_cast<const float4*>(&Qs[(i0 + r) * PADK + d4]);
#pragma unroll
            for (int c = 0; c < 4; c++)
                kf[c] = *reinterpret_cast<const float4*>(&Ks[(tx + 16 * c) * PADK + d4]);
#pragma unroll
            for (int r = 0; r < 4; r++)
#pragma unroll
                for (int c = 0; c < 4; c++) {
                    S[r][c] = fmaf(qf[r].x, kf[c].x, S[r][c]);
                    S[r][c] = fmaf(qf[r].y, kf[c].y, S[r][c]);
                    S[r][c] = fmaf(qf[r].z, kf[c].z, S[r][c]);
                    S[r][c] = fmaf(qf[r].w, kf[c].w, S[r][c]);
                }
        }

        // Online softmax (row stats shared across the 16 tx lanes via shfl)
        const bool diag = (kt == qtile);
#pragma unroll
        for (int r = 0; r < 4; r++) {
#pragma unroll
            for (int c = 0; c < 4; c++) {
                float s = S[r][c] * scale;
                if (diag && (tx + 16 * c > i0 + r)) s = -1e30f;
                S[r][c] = s;
            }
            float mx = fmaxf(fmaxf(S[r][0], S[r][1]), fmaxf(S[r][2], S[r][3]));
#pragma unroll
            for (int w = 1; w < 16; w <<= 1)
                mx = fmaxf(mx, __shfl_xor_sync(0xffffffffu, mx, w));
            const float mnew  = fmaxf(m_r[r], mx);
            const float alpha = __expf(m_r[r] - mnew);
            m_r[r] = mnew;
            float rs = 0.0f;
#pragma unroll
            for (int c = 0; c < 4; c++) {
                const float p = __expf(S[r][c] - mnew);
                S[r][c] = p;
                rs += p;
            }
#pragma unroll
            for (int w = 1; w < 16; w <<= 1)
                rs += __shfl_xor_sync(0xffffffffu, rs, w);
            l_r[r] = l_r[r] * alpha + rs;
#pragma unroll
            for (int c = 0; c < 4; c++) O_r[r][c] *= alpha;
            // Scatter P: row (i0+r), cols tx+16c  (conflict-free with PADK=68)
#pragma unroll
            for (int c = 0; c < 4; c++)
                Ps[(i0 + r) * PADK + tx + 16 * c] = S[r][c];
        }
        __syncthreads();

        // O += P @ V  (dot-product form; thread d-cols d0..d0+3)
#pragma unroll
        for (int j4 = 0; j4 < 64; j4 += 4) {
            float4 pf[4], vf[4];
#pragma unroll
            for (int r = 0; r < 4; r++)
                pf[r] = *reinterpret_cast<const float4*>(&Ps[(i0 + r) * PADK + j4]);
#pragma unroll
            for (int jj = 0; jj < 4; jj++)
                vf[jj] = *reinterpret_cast<const float4*>(&Vs[(j4 + jj) * PADK + d0]);
#pragma unroll
            for (int r = 0; r < 4; r++) {
                const float pr[4] = {pf[r].x, pf[r].y, pf[r].z, pf[r].w};
#pragma unroll
                for (int jj = 0; jj < 4; jj++) {
                    O_r[r][0] = fmaf(pr[jj], vf[jj].x, O_r[r][0]);
                    O_r[r][1] = fmaf(pr[jj], vf[jj].y, O_r[r][1]);
                    O_r[r][2] = fmaf(pr[jj], vf[jj].z, O_r[r][2]);
                    O_r[r][3] = fmaf(pr[jj], vf[jj].w, O_r[r][3]);
                }
            }
        }
    }

    // Normalize and write y[t, h*64 + d]
#pragma unroll
    for (int r = 0; r < 4; r++) {
        const float inv = 1.0f / l_r[r];
        float4 o;
        o.x = O_r[r][0] * inv;
        o.y = O_r[r][1] * inv;
        o.z = O_r[r][2] * inv;
        o.w = O_r[r][3] * inv;
        *reinterpret_cast<float4*>(
            &g_y[(size_t)(q0 + i0 + r) * CDIM + h * DHEAD + d0]) = o;
    }
}

// ----------------------------------------------------------------------------
// Launch: x -> (QKV gemm) -> g_qkv -> (flash attn) -> g_y -> (proj gemm) -> out
// Inputs (metadata order): x, mask(unused: causal is structural), W_qkv, b_qkv,
// W_proj, b_proj. Output: fp32 [1,4096,768].
// ----------------------------------------------------------------------------
extern "C" void kernel_launch(void* const* d_in, const int* in_sizes, int n_in,
                              void* d_out, int out_size)
{
    const float* x      = (const float*)d_in[0];
    const float* W_qkv  = (const float*)d_in[2];
    const float* b_qkv  = (const float*)d_in[3];
    const float* W_proj = (const float*)d_in[4];
    const float* b_proj = (const float*)d_in[5];
    float* out = (float*)d_out;

    // 1) QKV projection: [4096,768] @ [768,2304] + b -> g_qkv
    {
        dim3 grid(QKVN / GBN, TSEQ / GBM);
        sgemm_bias<0><<<grid, 256>>>(x, W_qkv, b_qkv, nullptr, TSEQ, QKVN, CDIM);
    }

    // 2) Causal flash attention -> g_y
    {
        constexpr int smem_bytes = 4 * 64 * PADK * (int)sizeof(float);  // 69632
        cudaFuncSetAttribute(flash_attn,
                             cudaFuncAttributeMaxDynamicSharedMemorySize,
                             smem_bytes);
        dim3 grid(TSEQ / 64, NHEAD);
        flash_attn<<<grid, 256, smem_bytes>>>();
    }

    // 3) Output projection: [4096,768] @ [768,768] + b -> out
    {
        dim3 grid(CDIM / GBN, TSEQ / GBM);
        sgemm_bias<1><<<grid, 256>>>(nullptr, W_proj, b_proj, out, TSEQ, CDIM, CDIM);
    }
}

// round 5
// speedup vs baseline: 1.0881x; 1.0881x over previous
#include <cuda_runtime.h>

// Problem constants (B=1)
#define TSEQ   4096
#define CDIM   768
#define NHEAD  12
#define DHEAD  64
#define QKVN   2304   // 3*C

// Scratch (allocation-free rule: __device__ globals)
__device__ float g_qkv[TSEQ * QKVN];   // [T, 3C]  (q | k | v)
__device__ float g_y[TSEQ * CDIM];     // [T, C]   attention output

// ----------------------------------------------------------------------------
// SGEMM with bias:  C[M,N] = A[M,K] @ B[K,N] + bias[N]   (unchanged, FFMA)
// ----------------------------------------------------------------------------
#define GBM 128
#define GBN 128
#define GBK 8
#define GTM 8
#define GTN 8

template <int MODE>
__global__ __launch_bounds__(256, 2)
void sgemm_bias(const float* __restrict__ Ain, const float* __restrict__ B,
                const float* __restrict__ bias, float* __restrict__ Cout,
                int M, int N, int K)
{
    const float* A = (MODE == 0) ? Ain : g_y;
    float*       C = (MODE == 0) ? g_qkv : Cout;

    __shared__ float As[GBK][GBM];   // k-major (transposed)
    __shared__ float Bs[GBK][GBN];

    const int tid  = threadIdx.x;
    const int brow = blockIdx.y * GBM;
    const int bcol = blockIdx.x * GBN;
    const int trow = (tid >> 4) * GTM;
    const int tcol = (tid & 15) * GTN;

    const int a_row = tid >> 1;
    const int a_k   = (tid & 1) * 4;
    const int b_row = tid >> 5;
    const int b_col = (tid & 31) * 4;

    float acc[GTM][GTN];
#pragma unroll
    for (int i = 0; i < GTM; i++)
#pragma unroll
        for (int j = 0; j < GTN; j++) acc[i][j] = 0.0f;

    const float* Aptr = A + (size_t)(brow + a_row) * K + a_k;
    const float* Bptr = B + (size_t)b_row * N + bcol + b_col;

    for (int k0 = 0; k0 < K; k0 += GBK) {
        const float4 av = *reinterpret_cast<const float4*>(Aptr + k0);
        const float4 bv = *reinterpret_cast<const float4*>(Bptr + (size_t)k0 * N);
        As[a_k + 0][a_row] = av.x;
        As[a_k + 1][a_row] = av.y;
        As[a_k + 2][a_row] = av.z;
        As[a_k + 3][a_row] = av.w;
        *reinterpret_cast<float4*>(&Bs[b_row][b_col]) = bv;
        __syncthreads();

#pragma unroll
        for (int kk = 0; kk < GBK; kk++) {
            const float4 a0 = *reinterpret_cast<const float4*>(&As[kk][trow]);
            const float4 a1 = *reinterpret_cast<const float4*>(&As[kk][trow + 4]);
            const float4 b0 = *reinterpret_cast<const float4*>(&Bs[kk][tcol]);
            const float4 b1 = *reinterpret_cast<const float4*>(&Bs[kk][tcol + 4]);
            const float ar[8] = {a0.x, a0.y, a0.z, a0.w, a1.x, a1.y, a1.z, a1.w};
            const float br[8] = {b0.x, b0.y, b0.z, b0.w, b1.x, b1.y, b1.z, b1.w};
#pragma unroll
            for (int i = 0; i < GTM; i++)
#pragma unroll
                for (int j = 0; j < GTN; j++)
                    acc[i][j] = fmaf(ar[i], br[j], acc[i][j]);
        }
        __syncthreads();
    }

#pragma unroll
    for (int i = 0; i < GTM; i++) {
        float* crow = C + (size_t)(brow + trow + i) * N + bcol + tcol;
#pragma unroll
        for (int j = 0; j < GTN; j += 4) {
            float4 o;
            o.x = acc[i][j + 0] + bias[bcol + tcol + j + 0];
            o.y = acc[i][j + 1] + bias[bcol + tcol + j + 1];
            o.z = acc[i][j + 2] + bias[bcol + tcol + j + 2];
            o.w = acc[i][j + 3] + bias[bcol + tcol + j + 3];
            *reinterpret_cast<float4*>(crow + j) = o;
        }
    }
}

// ----------------------------------------------------------------------------
// Causal flash attention on tensor cores (tf32 mma.sync.m16n8k8).
// Block = (head, 64-row q-tile), 128 threads = 4 warps x 16 q-rows.
// Strides: Qs/Ks/Ps = 68 (fragment reads hit banks 4*grp+qid: conflict-free),
//          Vs = 72       (fragment reads hit banks 8*qid+grp: conflict-free).
// Q pre-scaled by 0.125*log2(e) so softmax uses raw ex2.approx.
// P re-fragmenting via smem is warp-local (rows disjoint per warp): __syncwarp.
// ----------------------------------------------------------------------------
#define QK_STRIDE 68
#define V_STRIDE  72

__device__ __forceinline__ float ftf32(float x) {
    asm("cvt.rna.tf32.f32 %0, %0;" : "+f"(x));
    return x;
}
__device__ __forceinline__ float ex2f_fast(float x) {
    float y; asm("ex2.approx.f32 %0, %1;" : "=f"(y) : "f"(x)); return y;
}
__device__ __forceinline__ void mma_tf32(float d[4], const unsigned a[4], const unsigned b[2]) {
    asm volatile(
        "mma.sync.aligned.m16n8k8.row.col.f32.tf32.tf32.f32 "
        "{%0,%1,%2,%3}, {%4,%5,%6,%7}, {%8,%9}, {%0,%1,%2,%3};\n"
        : "+f"(d[0]), "+f"(d[1]), "+f"(d[2]), "+f"(d[3])
        : "r"(a[0]), "r"(a[1]), "r"(a[2]), "r"(a[3]), "r"(b[0]), "r"(b[1]));
}

__global__ __launch_bounds__(128)
void flash_attn_tf32()
{
    extern __shared__ float sm[];
    float* Qs = sm;                         // [64][68]
    float* Ks = Qs + 64 * QK_STRIDE;        // [64][68]
    float* Vs = Ks + 64 * QK_STRIDE;        // [64][72]
    float* Ps = Vs + 64 * V_STRIDE;         // [64][68]

    const int h     = blockIdx.y;
    const int qtile = gridDim.x - 1 - blockIdx.x;   // heavy tiles first
    const int q0    = qtile * 64;
    const int tid   = threadIdx.x;
    const int warp  = tid >> 5;
    const int lane  = tid & 31;
    const int grp   = lane >> 2;   // 0..7
    const int qid   = lane & 3;    // 0..3
    const int i0    = warp * 16;   // warp's q-row base within tile

    // Load + prescale Q (base-2 logits: fold 1/sqrt(D) and log2(e))
    const float QSCALE = 0.125f * 1.4426950408889634f;
    for (int it = 0; it < 8; it++) {
        const int idx = it * 128 + tid;
        const int row = idx >> 4;
        const int c4  = (idx & 15) << 2;
        float4 v = *reinterpret_cast<const float4*>(
            &g_qkv[(size_t)(q0 + row) * QKVN + h * DHEAD + c4]);
        v.x = ftf32(v.x * QSCALE); v.y = ftf32(v.y * QSCALE);
        v.z = ftf32(v.z * QSCALE); v.w = ftf32(v.w * QSCALE);
        *reinterpret_cast<float4*>(&Qs[row * QK_STRIDE + c4]) = v;
    }

    float O[8][4];
#pragma unroll
    for (int dt = 0; dt < 8; dt++)
#pragma unroll
        for (int c = 0; c < 4; c++) O[dt][c] = 0.0f;
    float m0 = -1e30f, m1 = -1e30f, l0 = 0.0f, l1 = 0.0f;

    const unsigned* Qu = reinterpret_cast<const unsigned*>(Qs);
    const unsigned* Ku = reinterpret_cast<const unsigned*>(Ks);
    const unsigned* Vu = reinterpret_cast<const unsigned*>(Vs);
    const unsigned* Pu = reinterpret_cast<const unsigned*>(Ps);

    for (int kt = 0; kt <= qtile; kt++) {
        const int k0 = kt * 64;
        __syncthreads();   // previous iter done reading Ks/Vs
        for (int it = 0; it < 8; it++) {
            const int idx = it * 128 + tid;
            const int row = idx >> 4;
            const int c4  = (idx & 15) << 2;
            const float* bp = &g_qkv[(size_t)(k0 + row) * QKVN + h * DHEAD + c4];
            float4 kv = *reinterpret_cast<const float4*>(bp + CDIM);
            float4 vv = *reinterpret_cast<const float4*>(bp + 2 * CDIM);
            kv.x = ftf32(kv.x); kv.y = ftf32(kv.y); kv.z = ftf32(kv.z); kv.w = ftf32(kv.w);
            vv.x = ftf32(vv.x); vv.y = ftf32(vv.y); vv.z = ftf32(vv.z); vv.w = ftf32(vv.w);
            *reinterpret_cast<float4*>(&Ks[row * QK_STRIDE + c4]) = kv;
            *reinterpret_cast<float4*>(&Vs[row * V_STRIDE  + c4]) = vv;
        }
        __syncthreads();

        // ---- S = Q K^T  (8 n-tiles of m16n8, k = 64 in 8 steps) ----
        float S[8][4];
#pragma unroll
        for (int nt = 0; nt < 8; nt++)
#pragma unroll
            for (int c = 0; c < 4; c++) S[nt][c] = 0.0f;

#pragma unroll
        for (int kk = 0; kk < 8; kk++) {
            unsigned a[4];
            const int ai = (i0 + grp) * QK_STRIDE + kk * 8 + qid;
            a[0] = Qu[ai];
            a[1] = Qu[ai + 8 * QK_STRIDE];
            a[2] = Qu[ai + 4];
            a[3] = Qu[ai + 8 * QK_STRIDE + 4];
#pragma unroll
            for (int nt = 0; nt < 8; nt++) {
                unsigned b[2];
                const int bi = (nt * 8 + grp) * QK_STRIDE + kk * 8 + qid;
                b[0] = Ku[bi];
                b[1] = Ku[bi + 4];
                mma_tf32(S[nt], a, b);
            }
        }

        // ---- causal mask on diagonal tile ----
        const int r0 = i0 + grp;
        const int r1 = r0 + 8;
        if (kt == qtile) {
#pragma unroll
            for (int nt = 0; nt < 8; nt++) {
                const int j0 = nt * 8 + 2 * qid;
                if (j0     > r0) S[nt][0] = -1e30f;
                if (j0 + 1 > r0) S[nt][1] = -1e30f;
                if (j0     > r1) S[nt][2] = -1e30f;
                if (j0 + 1 > r1) S[nt][3] = -1e30f;
            }
        }

        // ---- online softmax (base-2), row stats across 4 quad-lanes ----
        float mx0 = -1e30f, mx1 = -1e30f;
#pragma unroll
        for (int nt = 0; nt < 8; nt++) {
            mx0 = fmaxf(mx0, fmaxf(S[nt][0], S[nt][1]));
            mx1 = fmaxf(mx1, fmaxf(S[nt][2], S[nt][3]));
        }
        mx0 = fmaxf(mx0, __shfl_xor_sync(0xffffffffu, mx0, 1));
        mx0 = fmaxf(mx0, __shfl_xor_sync(0xffffffffu, mx0, 2));
        mx1 = fmaxf(mx1, __shfl_xor_sync(0xffffffffu, mx1, 1));
        mx1 = fmaxf(mx1, __shfl_xor_sync(0xffffffffu, mx1, 2));

        const float mn0 = fmaxf(m0, mx0);
        const float mn1 = fmaxf(m1, mx1);
        const float al0 = ex2f_fast(m0 - mn0);
        const float al1 = ex2f_fast(m1 - mn1);
        m0 = mn0; m1 = mn1;

        float rs0 = 0.0f, rs1 = 0.0f;
#pragma unroll
        for (int nt = 0; nt < 8; nt++) {
            S[nt][0] = ex2f_fast(S[nt][0] - mn0); rs0 += S[nt][0];
            S[nt][1] = ex2f_fast(S[nt][1] - mn0); rs0 += S[nt][1];
            S[nt][2] = ex2f_fast(S[nt][2] - mn1); rs1 += S[nt][2];
            S[nt][3] = ex2f_fast(S[nt][3] - mn1); rs1 += S[nt][3];
        }
        rs0 += __shfl_xor_sync(0xffffffffu, rs0, 1);
        rs0 += __shfl_xor_sync(0xffffffffu, rs0, 2);
        rs1 += __shfl_xor_sync(0xffffffffu, rs1, 1);
        rs1 += __shfl_xor_sync(0xffffffffu, rs1, 2);
        l0 = l0 * al0 + rs0;
        l1 = l1 * al1 + rs1;

#pragma unroll
        for (int dt = 0; dt < 8; dt++) {
            O[dt][0] *= al0; O[dt][1] *= al0;
            O[dt][2] *= al1; O[dt][3] *= al1;
        }

        // ---- scatter P (warp-local rows) and re-fragment as A operand ----
        {
            float* p0 = &Ps[r0 * QK_STRIDE + 2 * qid];
            float* p1 = &Ps[r1 * QK_STRIDE + 2 * qid];
#pragma unroll
            for (int nt = 0; nt < 8; nt++) {
                float2 w0 = make_float2(ftf32(S[nt][0]), ftf32(S[nt][1]));
                float2 w1 = make_float2(ftf32(S[nt][2]), ftf32(S[nt][3]));
                *reinterpret_cast<float2*>(p0 + nt * 8) = w0;
                *reinterpret_cast<float2*>(p1 + nt * 8) = w1;
            }
        }
        __syncwarp();

        // ---- O += P V  (k = key index, 8 steps; 8 d-tiles) ----
#pragma unroll
        for (int kk = 0; kk < 8; kk++) {
            unsigned a[4];
            const int ai = (i0 + grp) * QK_STRIDE + kk * 8 + qid;
            a[0] = Pu[ai];
            a[1] = Pu[ai + 8 * QK_STRIDE];
            a[2] = Pu[ai + 4];
            a[3] = Pu[ai + 8 * QK_STRIDE + 4];
#pragma unroll
            for (int dt = 0; dt < 8; dt++) {
                unsigned b[2];
                const int bi = (kk * 8 + qid) * V_STRIDE + dt * 8 + grp;
                b[0] = Vu[bi];
                b[1] = Vu[bi + 4 * V_STRIDE];
                mma_tf32(O[dt], a, b);
            }
        }
        __syncwarp();   // Ps reads done before next iter's writes
    }

    // ---- normalize and store y[t, h*64 + d] ----
    const float inv0 = 1.0f / l0;
    const float inv1 = 1.0f / l1;
    const int gr0 = q0 + i0 + grp;
#pragma unroll
    for (int dt = 0; dt < 8; dt++) {
        const int coff = h * DHEAD + dt * 8 + 2 * qid;
        float2 o0 = make_float2(O[dt][0] * inv0, O[dt][1] * inv0);
        float2 o1 = make_float2(O[dt][2] * inv1, O[dt][3] * inv1);
        *reinterpret_cast<float2*>(&g_y[(size_t)gr0 * CDIM + coff])       = o0;
        *reinterpret_cast<float2*>(&g_y[(size_t)(gr0 + 8) * CDIM + coff]) = o1;
    }
}

// ----------------------------------------------------------------------------
// Launch
// ----------------------------------------------------------------------------
extern "C" void kernel_launch(void* const* d_in, const int* in_sizes, int n_in,
                              void* d_out, int out_size)
{
    const float* x      = (const float*)d_in[0];
    const float* W_qkv  = (const float*)d_in[2];
    const float* b_qkv  = (const float*)d_in[3];
    const float* W_proj = (const float*)d_in[4];
    const float* b_proj = (const float*)d_in[5];
    float* out = (float*)d_out;

    // 1) QKV projection
    {
        dim3 grid(QKVN / GBN, TSEQ / GBM);
        sgemm_bias<0><<<grid, 256>>>(x, W_qkv, b_qkv, nullptr, TSEQ, QKVN, CDIM);
    }

    // 2) Causal flash attention (tf32 tensor cores)
    {
        constexpr int smem_bytes =
            (64 * QK_STRIDE * 3 + 64 * V_STRIDE) * (int)sizeof(float);  // 70656
        cudaFuncSetAttribute(flash_attn_tf32,
                             cudaFuncAttributeMaxDynamicSharedMemorySize,
                             smem_bytes);
        dim3 grid(TSEQ / 64, NHEAD);
        flash_attn_tf32<<<grid, 128, smem_bytes>>>();
    }

    // 3) Output projection
    {
        dim3 grid(CDIM / GBN, TSEQ / GBM);
        sgemm_bias<1><<<grid, 256>>>(nullptr, W_proj, b_proj, out, TSEQ, CDIM, CDIM);
    }
}

// round 12
// speedup vs baseline: 2.3544x; 2.1639x over previous
#include <cuda_runtime.h>
#include <cuda_bf16.h>
#include <cstdint>

// Problem constants (B=1)
#define TSEQ   4096
#define CDIM   768
#define NHEAD  12
#define DHEAD  64
#define QKVN   2304   // 3*C

// ---------------------------------------------------------------------------
// Scratch (allocation-free rule: __device__ globals).
// IMPORTANT: these are referenced ONLY from device code (template MODE
// selection) — passing them as host-side kernel args is UB and was the R11 bug.
// ---------------------------------------------------------------------------
__device__ float g_qkv[TSEQ * QKVN];   // [T, 3C]  (q | k | v)  fp32

__device__ __align__(16) __nv_bfloat16 g_xh[TSEQ * CDIM];
__device__ __align__(16) __nv_bfloat16 g_xl[TSEQ * CDIM];
__device__ __align__(16) __nv_bfloat16 g_yh[TSEQ * CDIM];   // attn out hi
__device__ __align__(16) __nv_bfloat16 g_yl[TSEQ * CDIM];   // attn out lo
__device__ __align__(16) __nv_bfloat16 g_wqh[QKVN * CDIM];  // W_qkv^T [2304][768]
__device__ __align__(16) __nv_bfloat16 g_wql[QKVN * CDIM];
__device__ __align__(16) __nv_bfloat16 g_wph[CDIM * CDIM];  // W_proj^T [768][768]
__device__ __align__(16) __nv_bfloat16 g_wpl[CDIM * CDIM];

// ---------------------------------------------------------------------------
// fp32 -> bf16 hi/lo split of x (outputs are device globals, device-selected)
// ---------------------------------------------------------------------------
__global__ void split_x(const float* __restrict__ in, int n4)
{
    __nv_bfloat16* __restrict__ oh = g_xh;
    __nv_bfloat16* __restrict__ ol = g_xl;
    const int i = blockIdx.x * blockDim.x + threadIdx.x;
    if (i >= n4) return;
    const float4 v = reinterpret_cast<const float4*>(in)[i];
    __nv_bfloat16 h0 = __float2bfloat16(v.x), h1 = __float2bfloat16(v.y);
    __nv_bfloat16 h2 = __float2bfloat16(v.z), h3 = __float2bfloat16(v.w);
    reinterpret_cast<__nv_bfloat162*>(oh)[2 * i]     = __nv_bfloat162(h0, h1);
    reinterpret_cast<__nv_bfloat162*>(oh)[2 * i + 1] = __nv_bfloat162(h2, h3);
    reinterpret_cast<__nv_bfloat162*>(ol)[2 * i] =
        __nv_bfloat162(__float2bfloat16(v.x - __bfloat162float(h0)),
                       __float2bfloat16(v.y - __bfloat162float(h1)));
    reinterpret_cast<__nv_bfloat162*>(ol)[2 * i + 1] =
        __nv_bfloat162(__float2bfloat16(v.z - __bfloat162float(h2)),
                       __float2bfloat16(v.w - __bfloat162float(h3)));
}

// W [K][N] fp32 -> [N][K] bf16 hi/lo (transpose + split).
// MODE 0: -> g_wqh/g_wql ; MODE 1: -> g_wph/g_wpl
template <int MODE>
__global__ void transpose_split(const float* __restrict__ W, int K, int N)
{
    __nv_bfloat16* __restrict__ oh = (MODE == 0) ? g_wqh : g_wph;
    __nv_bfloat16* __restrict__ ol = (MODE == 0) ? g_wql : g_wpl;
    __shared__ float t[32][33];
    const int nx = blockIdx.x * 32, ky = blockIdx.y * 32;
    const int txx = threadIdx.x, tyy = threadIdx.y;
#pragma unroll
    for (int j = 0; j < 32; j += 8)
        t[tyy + j][txx] = W[(size_t)(ky + tyy + j) * N + nx + txx];
    __syncthreads();
#pragma unroll
    for (int j = 0; j < 32; j += 8) {
        const float v = t[txx][tyy + j];
        const __nv_bfloat16 h = __float2bfloat16(v);
        oh[(size_t)(nx + tyy + j) * K + ky + txx] = h;
        ol[(size_t)(nx + tyy + j) * K + ky + txx] =
            __float2bfloat16(v - __bfloat162float(h));
    }
}

// ---------------------------------------------------------------------------
// bf16 split GEMM on mma.sync.m16n8k16:
//   C[M,N] = Ah*Bh + Ah*Bl + Al*Bh + bias   (fp32 accumulate)
// A [M][K] k-major bf16, B [N][K] k-major bf16 (= W^T).
// CTA: 128x128, 8 warps (2x4), warp tile 64x32, BK=64.
// Smem b32 row stride 36 -> fragment LDS hits banks 4*grp+qid (conflict-free).
// MODE 0: A=g_xh/g_xl, B=g_wqh/g_wql, C=g_qkv (Cout unused)
// MODE 1: A=g_yh/g_yl, B=g_wph/g_wpl, C=Cout (harness out pointer)
// ---------------------------------------------------------------------------
#define KSTR 36   // b32 per smem row

__device__ __forceinline__ void mma_bf16(float d[4], const uint32_t a[4],
                                         const uint32_t b[2]) {
    asm volatile(
        "mma.sync.aligned.m16n8k16.row.col.f32.bf16.bf16.f32 "
        "{%0,%1,%2,%3}, {%4,%5,%6,%7}, {%8,%9}, {%0,%1,%2,%3};\n"
        : "+f"(d[0]), "+f"(d[1]), "+f"(d[2]), "+f"(d[3])
        : "r"(a[0]), "r"(a[1]), "r"(a[2]), "r"(a[3]), "r"(b[0]), "r"(b[1]));
}

template <int MODE>
__global__ __launch_bounds__(256)
void gemm_bf16(const float* __restrict__ bias, float* __restrict__ Cout,
               int M, int N, int K)
{
    const __nv_bfloat16* __restrict__ Ah = (MODE == 0) ? g_xh : g_yh;
    const __nv_bfloat16* __restrict__ Al = (MODE == 0) ? g_xl : g_yl;
    const __nv_bfloat16* __restrict__ Bh = (MODE == 0) ? g_wqh : g_wph;
    const __nv_bfloat16* __restrict__ Bl = (MODE == 0) ? g_wql : g_wpl;
    float* __restrict__ C = (MODE == 0) ? g_qkv : Cout;

    extern __shared__ uint32_t sg[];
    uint32_t* sAh = sg;                    // [128][KSTR] b32
    uint32_t* sAl = sAh + 128 * KSTR;
    uint32_t* sBh = sAl + 128 * KSTR;
    uint32_t* sBl = sBh + 128 * KSTR;

    const int tid  = threadIdx.x;
    const int warp = tid >> 5;
    const int lane = tid & 31;
    const int grp  = lane >> 2;    // 0..7
    const int qid  = lane & 3;     // 0..3
    const int wy   = warp >> 2;    // 0..1  -> row offset 64
    const int wx   = warp & 3;     // 0..3  -> col offset 32
    const int brow = blockIdx.y * 128;
    const int bcol = blockIdx.x * 128;

    float Cacc[4][4][4];
#pragma unroll
    for (int mt = 0; mt < 4; mt++)
#pragma unroll
        for (int nt = 0; nt < 4; nt++)
#pragma unroll
            for (int c = 0; c < 4; c++) Cacc[mt][nt][c] = 0.0f;

    for (int kofs = 0; kofs < K; kofs += 64) {
        __syncthreads();
        // 256 threads x 4 uint4 per array = 128 rows x 8 units (16B each)
#pragma unroll
        for (int it = 0; it < 4; it++) {
            const int idx = it * 256 + tid;
            const int row = idx >> 3;          // 0..127
            const int u   = idx & 7;           // uint4 unit (8 bf16)
            const size_t ga = (size_t)(brow + row) * K + kofs + u * 8;
            const size_t gb = (size_t)(bcol + row) * K + kofs + u * 8;
            const uint4 vah = *reinterpret_cast<const uint4*>(Ah + ga);
            const uint4 val = *reinterpret_cast<const uint4*>(Al + ga);
            const uint4 vbh = *reinterpret_cast<const uint4*>(Bh + gb);
            const uint4 vbl = *reinterpret_cast<const uint4*>(Bl + gb);
            const int so = row * KSTR + u * 4;
            *reinterpret_cast<uint4*>(sAh + so) = vah;
            *reinterpret_cast<uint4*>(sAl + so) = val;
            *reinterpret_cast<uint4*>(sBh + so) = vbh;
            *reinterpret_cast<uint4*>(sBl + so) = vbl;
        }
        __syncthreads();

#pragma unroll
        for (int kk = 0; kk < 4; kk++) {       // 4 x k16
            const int kb = kk * 8;             // b32 col base
            uint32_t bh[4][2], bl[4][2];
#pragma unroll
            for (int nt = 0; nt < 4; nt++) {
                const int n = wx * 32 + nt * 8 + grp;
                bh[nt][0] = sBh[n * KSTR + kb + qid];
                bh[nt][1] = sBh[n * KSTR + kb + 4 + qid];
                bl[nt][0] = sBl[n * KSTR + kb + qid];
                bl[nt][1] = sBl[n * KSTR + kb + 4 + qid];
            }
#pragma unroll
            for (int mt = 0; mt < 4; mt++) {
                const int r0 = wy * 64 + mt * 16 + grp;
                uint32_t ah[4], al[4];
                ah[0] = sAh[r0 * KSTR + kb + qid];
                ah[1] = sAh[(r0 + 8) * KSTR + kb + qid];
                ah[2] = sAh[r0 * KSTR + kb + 4 + qid];
                ah[3] = sAh[(r0 + 8) * KSTR + kb + 4 + qid];
                al[0] = sAl[r0 * KSTR + kb + qid];
                al[1] = sAl[(r0 + 8) * KSTR + kb + qid];
                al[2] = sAl[r0 * KSTR + kb + 4 + qid];
                al[3] = sAl[(r0 + 8) * KSTR + kb + 4 + qid];
#pragma unroll
                for (int nt = 0; nt < 4; nt++) {
                    mma_bf16(Cacc[mt][nt], ah, bh[nt]);
                    mma_bf16(Cacc[mt][nt], ah, bl[nt]);
                    mma_bf16(Cacc[mt][nt], al, bh[nt]);
                }
            }
        }
    }

    // Epilogue: bias + store fp32
#pragma unroll
    for (int mt = 0; mt < 4; mt++) {
        const int r0 = brow + wy * 64 + mt * 16 + grp;
#pragma unroll
        for (int nt = 0; nt < 4; nt++) {
            const int cc = bcol + wx * 32 + nt * 8 + 2 * qid;
            const float b0 = bias[cc], b1 = bias[cc + 1];
            float2 o0 = make_float2(Cacc[mt][nt][0] + b0, Cacc[mt][nt][1] + b1);
            float2 o1 = make_float2(Cacc[mt][nt][2] + b0, Cacc[mt][nt][3] + b1);
            *reinterpret_cast<float2*>(&C[(size_t)r0 * N + cc])       = o0;
            *reinterpret_cast<float2*>(&C[(size_t)(r0 + 8) * N + cc]) = o1;
        }
    }
}

// ----------------------------------------------------------------------------
// Causal flash attention on tensor cores (tf32 mma.sync.m16n8k8).
// Epilogue writes bf16 hi/lo directly into g_yh/g_yl (device globals).
// ----------------------------------------------------------------------------
#define QK_STRIDE 68
#define V_STRIDE  72

__device__ __forceinline__ float ftf32(float x) {
    asm("cvt.rna.tf32.f32 %0, %0;" : "+f"(x));
    return x;
}
__device__ __forceinline__ float ex2f_fast(float x) {
    float y; asm("ex2.approx.f32 %0, %1;" : "=f"(y) : "f"(x)); return y;
}
__device__ __forceinline__ void mma_tf32(float d[4], const unsigned a[4], const unsigned b[2]) {
    asm volatile(
        "mma.sync.aligned.m16n8k8.row.col.f32.tf32.tf32.f32 "
        "{%0,%1,%2,%3}, {%4,%5,%6,%7}, {%8,%9}, {%0,%1,%2,%3};\n"
        : "+f"(d[0]), "+f"(d[1]), "+f"(d[2]), "+f"(d[3])
        : "r"(a[0]), "r"(a[1]), "r"(a[2]), "r"(a[3]), "r"(b[0]), "r"(b[1]));
}

__global__ __launch_bounds__(128)
void flash_attn_tf32()
{
    extern __shared__ float sm[];
    float* Qs = sm;
    float* Ks = Qs + 64 * QK_STRIDE;
    float* Vs = Ks + 64 * QK_STRIDE;
    float* Ps = Vs + 64 * V_STRIDE;

    const int h     = blockIdx.y;
    const int qtile = gridDim.x - 1 - blockIdx.x;
    const int q0    = qtile * 64;
    const int tid   = threadIdx.x;
    const int warp  = tid >> 5;
    const int lane  = tid & 31;
    const int grp   = lane >> 2;
    const int qid   = lane & 3;
    const int i0    = warp * 16;

    const float QSCALE = 0.125f * 1.4426950408889634f;
    for (int it = 0; it < 8; it++) {
        const int idx = it * 128 + tid;
        const int row = idx >> 4;
        const int c4  = (idx & 15) << 2;
        float4 v = *reinterpret_cast<const float4*>(
            &g_qkv[(size_t)(q0 + row) * QKVN + h * DHEAD + c4]);
        v.x = ftf32(v.x * QSCALE); v.y = ftf32(v.y * QSCALE);
        v.z = ftf32(v.z * QSCALE); v.w = ftf32(v.w * QSCALE);
        *reinterpret_cast<float4*>(&Qs[row * QK_STRIDE + c4]) = v;
    }

    float O[8][4];
#pragma unroll
    for (int dt = 0; dt < 8; dt++)
#pragma unroll
        for (int c = 0; c < 4; c++) O[dt][c] = 0.0f;
    float m0 = -1e30f, m1 = -1e30f, l0 = 0.0f, l1 = 0.0f;

    const unsigned* Qu = reinterpret_cast<const unsigned*>(Qs);
    const unsigned* Ku = reinterpret_cast<const unsigned*>(Ks);
    const unsigned* Vu = reinterpret_cast<const unsigned*>(Vs);
    const unsigned* Pu = reinterpret_cast<const unsigned*>(Ps);

    for (int kt = 0; kt <= qtile; kt++) {
        const int k0 = kt * 64;
        __syncthreads();
        for (int it = 0; it < 8; it++) {
            const int idx = it * 128 + tid;
            const int row = idx >> 4;
            const int c4  = (idx & 15) << 2;
            const float* bp = &g_qkv[(size_t)(k0 + row) * QKVN + h * DHEAD + c4];
            float4 kv = *reinterpret_cast<const float4*>(bp + CDIM);
            float4 vv = *reinterpret_cast<const float4*>(bp + 2 * CDIM);
            kv.x = ftf32(kv.x); kv.y = ftf32(kv.y); kv.z = ftf32(kv.z); kv.w = ftf32(kv.w);
            vv.x = ftf32(vv.x); vv.y = ftf32(vv.y); vv.z = ftf32(vv.z); vv.w = ftf32(vv.w);
            *reinterpret_cast<float4*>(&Ks[row * QK_STRIDE + c4]) = kv;
            *reinterpret_cast<float4*>(&Vs[row * V_STRIDE  + c4]) = vv;
        }
        __syncthreads();

        float S[8][4];
#pragma unroll
        for (int nt = 0; nt < 8; nt++)
#pragma unroll
            for (int c = 0; c < 4; c++) S[nt][c] = 0.0f;

#pragma unroll
        for (int kk = 0; kk < 8; kk++) {
            unsigned a[4];
            const int ai = (i0 + grp) * QK_STRIDE + kk * 8 + qid;
            a[0] = Qu[ai];
            a[1] = Qu[ai + 8 * QK_STRIDE];
            a[2] = Qu[ai + 4];
            a[3] = Qu[ai + 8 * QK_STRIDE + 4];
#pragma unroll
            for (int nt = 0; nt < 8; nt++) {
                unsigned b[2];
                const int bi = (nt * 8 + grp) * QK_STRIDE + kk * 8 + qid;
                b[0] = Ku[bi];
                b[1] = Ku[bi + 4];
                mma_tf32(S[nt], a, b);
            }
        }

        const int r0 = i0 + grp;
        const int r1 = r0 + 8;
        if (kt == qtile) {
#pragma unroll
            for (int nt = 0; nt < 8; nt++) {
                const int j0 = nt * 8 + 2 * qid;
                if (j0     > r0) S[nt][0] = -1e30f;
                if (j0 + 1 > r0) S[nt][1] = -1e30f;
                if (j0     > r1) S[nt][2] = -1e30f;
                if (j0 + 1 > r1) S[nt][3] = -1e30f;
            }
        }

        float mx0 = -1e30f, mx1 = -1e30f;
#pragma unroll
        for (int nt = 0; nt < 8; nt++) {
            mx0 = fmaxf(mx0, fmaxf(S[nt][0], S[nt][1]));
            mx1 = fmaxf(mx1, fmaxf(S[nt][2], S[nt][3]));
        }
        mx0 = fmaxf(mx0, __shfl_xor_sync(0xffffffffu, mx0, 1));
        mx0 = fmaxf(mx0, __shfl_xor_sync(0xffffffffu, mx0, 2));
        mx1 = fmaxf(mx1, __shfl_xor_sync(0xffffffffu, mx1, 1));
        mx1 = fmaxf(mx1, __shfl_xor_sync(0xffffffffu, mx1, 2));

        const float mn0 = fmaxf(m0, mx0);
        const float mn1 = fmaxf(m1, mx1);
        const float al0 = ex2f_fast(m0 - mn0);
        const float al1 = ex2f_fast(m1 - mn1);
        m0 = mn0; m1 = mn1;

        float rs0 = 0.0f, rs1 = 0.0f;
#pragma unroll
        for (int nt = 0; nt < 8; nt++) {
            S[nt][0] = ex2f_fast(S[nt][0] - mn0); rs0 += S[nt][0];
            S[nt][1] = ex2f_fast(S[nt][1] - mn0); rs0 += S[nt][1];
            S[nt][2] = ex2f_fast(S[nt][2] - mn1); rs1 += S[nt][2];
            S[nt][3] = ex2f_fast(S[nt][3] - mn1); rs1 += S[nt][3];
        }
        rs0 += __shfl_xor_sync(0xffffffffu, rs0, 1);
        rs0 += __shfl_xor_sync(0xffffffffu, rs0, 2);
        rs1 += __shfl_xor_sync(0xffffffffu, rs1, 1);
        rs1 += __shfl_xor_sync(0xffffffffu, rs1, 2);
        l0 = l0 * al0 + rs0;
        l1 = l1 * al1 + rs1;

#pragma unroll
        for (int dt = 0; dt < 8; dt++) {
            O[dt][0] *= al0; O[dt][1] *= al0;
            O[dt][2] *= al1; O[dt][3] *= al1;
        }

        {
            float* p0 = &Ps[r0 * QK_STRIDE + 2 * qid];
            float* p1 = &Ps[r1 * QK_STRIDE + 2 * qid];
#pragma unroll
            for (int nt = 0; nt < 8; nt++) {
                float2 w0 = make_float2(ftf32(S[nt][0]), ftf32(S[nt][1]));
                float2 w1 = make_float2(ftf32(S[nt][2]), ftf32(S[nt][3]));
                *reinterpret_cast<float2*>(p0 + nt * 8) = w0;
                *reinterpret_cast<float2*>(p1 + nt * 8) = w1;
            }
        }
        __syncwarp();

#pragma unroll
        for (int kk = 0; kk < 8; kk++) {
            unsigned a[4];
            const int ai = (i0 + grp) * QK_STRIDE + kk * 8 + qid;
            a[0] = Pu[ai];
            a[1] = Pu[ai + 8 * QK_STRIDE];
            a[2] = Pu[ai + 4];
            a[3] = Pu[ai + 8 * QK_STRIDE + 4];
#pragma unroll
            for (int dt = 0; dt < 8; dt++) {
                unsigned b[2];
                const int bi = (kk * 8 + qid) * V_STRIDE + dt * 8 + grp;
                b[0] = Vu[bi];
                b[1] = Vu[bi + 4 * V_STRIDE];
                mma_tf32(O[dt], a, b);
            }
        }
        __syncwarp();
    }

    // Normalize; write bf16 hi/lo pairs directly (coff even -> bf162-aligned)
    const float inv0 = 1.0f / l0;
    const float inv1 = 1.0f / l1;
    const int gr0 = q0 + i0 + grp;
    __nv_bfloat162* yh2 = reinterpret_cast<__nv_bfloat162*>(g_yh);
    __nv_bfloat162* yl2 = reinterpret_cast<__nv_bfloat162*>(g_yl);
#pragma unroll
    for (int dt = 0; dt < 8; dt++) {
        const int coff = h * DHEAD + dt * 8 + 2 * qid;
        const float v0 = O[dt][0] * inv0, v1 = O[dt][1] * inv0;
        const float v2 = O[dt][2] * inv1, v3 = O[dt][3] * inv1;
        const __nv_bfloat16 h0 = __float2bfloat16(v0), h1 = __float2bfloat16(v1);
        const __nv_bfloat16 h2 = __float2bfloat16(v2), h3 = __float2bfloat16(v3);
        const size_t p0 = ((size_t)gr0 * CDIM + coff) >> 1;
        const size_t p1 = ((size_t)(gr0 + 8) * CDIM + coff) >> 1;
        yh2[p0] = __nv_bfloat162(h0, h1);
        yh2[p1] = __nv_bfloat162(h2, h3);
        yl2[p0] = __nv_bfloat162(__float2bfloat16(v0 - __bfloat162float(h0)),
                                 __float2bfloat16(v1 - __bfloat162float(h1)));
        yl2[p1] = __nv_bfloat162(__float2bfloat16(v2 - __bfloat162float(h2)),
                                 __float2bfloat16(v3 - __bfloat162float(h3)));
    }
}

// ----------------------------------------------------------------------------
// Launch
// ----------------------------------------------------------------------------
extern "C" void kernel_launch(void* const* d_in, const int* in_sizes, int n_in,
                              void* d_out, int out_size)
{
    const float* x      = (const float*)d_in[0];
    const float* W_qkv  = (const float*)d_in[2];
    const float* b_qkv  = (const float*)d_in[3];
    const float* W_proj = (const float*)d_in[4];
    const float* b_proj = (const float*)d_in[5];
    float* out = (float*)d_out;

    constexpr int gemm_smem = 4 * 128 * KSTR * 4;   // 73728 bytes
    cudaFuncSetAttribute(gemm_bf16<0>, cudaFuncAttributeMaxDynamicSharedMemorySize,
                         gemm_smem);
    cudaFuncSetAttribute(gemm_bf16<1>, cudaFuncAttributeMaxDynamicSharedMemorySize,
                         gemm_smem);

    // 0) Pre-convert to bf16 hi/lo (globals selected in device code)
    {
        const int n4 = TSEQ * CDIM / 4;
        split_x<<<(n4 + 255) / 256, 256>>>(x, n4);
        transpose_split<0><<<dim3(QKVN / 32, CDIM / 32), dim3(32, 8)>>>(
            W_qkv, CDIM, QKVN);
        transpose_split<1><<<dim3(CDIM / 32, CDIM / 32), dim3(32, 8)>>>(
            W_proj, CDIM, CDIM);
    }

    // 1) QKV projection (bf16 split mma): [4096,768]@[768,2304]+b -> g_qkv
    {
        dim3 grid(QKVN / 128, TSEQ / 128);
        gemm_bf16<0><<<grid, 256, gemm_smem>>>(b_qkv, nullptr, TSEQ, QKVN, CDIM);
    }

    // 2) Causal flash attention (tf32) -> g_yh/g_yl (bf16 hi/lo fused)
    {
        constexpr int smem_bytes =
            (64 * QK_STRIDE * 3 + 64 * V_STRIDE) * (int)sizeof(float);  // 70656
        cudaFuncSetAttribute(flash_attn_tf32,
                             cudaFuncAttributeMaxDynamicSharedMemorySize,
                             smem_bytes);
        dim3 grid(TSEQ / 64, NHEAD);
        flash_attn_tf32<<<grid, 128, smem_bytes>>>();
    }

    // 3) Output projection (bf16 split mma): [4096,768]@[768,768]+b -> out
    {
        dim3 grid(CDIM / 128, TSEQ / 128);
        gemm_bf16<1><<<grid, 256, gemm_smem>>>(b_proj, out, TSEQ, CDIM, CDIM);
    }
}

// round 14
// speedup vs baseline: 2.5372x; 1.0776x over previous
#include <cuda_runtime.h>
#include <cuda_bf16.h>
#include <cstdint>

// Problem constants (B=1)
#define TSEQ   4096
#define CDIM   768
#define NHEAD  12
#define DHEAD  64
#define QKVN   2304   // 3*C

// ---------------------------------------------------------------------------
// Scratch (allocation-free rule: __device__ globals). Referenced ONLY from
// device code (template MODE selection) — host-side use of __device__ symbols
// as kernel args is UB (the R11 bug).
// ---------------------------------------------------------------------------
__device__ float g_qkv[TSEQ * QKVN];   // [T, 3C]  (q | k | v)  fp32

__device__ __align__(16) __nv_bfloat16 g_xh[TSEQ * CDIM];
__device__ __align__(16) __nv_bfloat16 g_xl[TSEQ * CDIM];
__device__ __align__(16) __nv_bfloat16 g_yh[TSEQ * CDIM];   // attn out hi
__device__ __align__(16) __nv_bfloat16 g_yl[TSEQ * CDIM];   // attn out lo
__device__ __align__(16) __nv_bfloat16 g_wqh[QKVN * CDIM];  // W_qkv^T
__device__ __align__(16) __nv_bfloat16 g_wql[QKVN * CDIM];
__device__ __align__(16) __nv_bfloat16 g_wph[CDIM * CDIM];  // W_proj^T
__device__ __align__(16) __nv_bfloat16 g_wpl[CDIM * CDIM];

// ---------------------------------------------------------------------------
// fp32 -> bf16 hi/lo split of x
// ---------------------------------------------------------------------------
__global__ void split_x(const float* __restrict__ in, int n4)
{
    __nv_bfloat16* __restrict__ oh = g_xh;
    __nv_bfloat16* __restrict__ ol = g_xl;
    const int i = blockIdx.x * blockDim.x + threadIdx.x;
    if (i >= n4) return;
    const float4 v = reinterpret_cast<const float4*>(in)[i];
    __nv_bfloat16 h0 = __float2bfloat16(v.x), h1 = __float2bfloat16(v.y);
    __nv_bfloat16 h2 = __float2bfloat16(v.z), h3 = __float2bfloat16(v.w);
    reinterpret_cast<__nv_bfloat162*>(oh)[2 * i]     = __nv_bfloat162(h0, h1);
    reinterpret_cast<__nv_bfloat162*>(oh)[2 * i + 1] = __nv_bfloat162(h2, h3);
    reinterpret_cast<__nv_bfloat162*>(ol)[2 * i] =
        __nv_bfloat162(__float2bfloat16(v.x - __bfloat162float(h0)),
                       __float2bfloat16(v.y - __bfloat162float(h1)));
    reinterpret_cast<__nv_bfloat162*>(ol)[2 * i + 1] =
        __nv_bfloat162(__float2bfloat16(v.z - __bfloat162float(h2)),
                       __float2bfloat16(v.w - __bfloat162float(h3)));
}

// W [K][N] fp32 -> [N][K] bf16 hi/lo (transpose + split).
template <int MODE>
__global__ void transpose_split(const float* __restrict__ W, int K, int N)
{
    __nv_bfloat16* __restrict__ oh = (MODE == 0) ? g_wqh : g_wph;
    __nv_bfloat16* __restrict__ ol = (MODE == 0) ? g_wql : g_wpl;
    __shared__ float t[32][33];
    const int nx = blockIdx.x * 32, ky = blockIdx.y * 32;
    const int txx = threadIdx.x, tyy = threadIdx.y;
#pragma unroll
    for (int j = 0; j < 32; j += 8)
        t[tyy + j][txx] = W[(size_t)(ky + tyy + j) * N + nx + txx];
    __syncthreads();
#pragma unroll
    for (int j = 0; j < 32; j += 8) {
        const float v = t[txx][tyy + j];
        const __nv_bfloat16 h = __float2bfloat16(v);
        oh[(size_t)(nx + tyy + j) * K + ky + txx] = h;
        ol[(size_t)(nx + tyy + j) * K + ky + txx] =
            __float2bfloat16(v - __bfloat162float(h));
    }
}

// ---------------------------------------------------------------------------
// bf16 split GEMM, cp.async double-buffered:
//   C[M,N] = Ah*Bh + Ah*Bl + Al*Bh + bias   (fp32 accumulate)
// CTA 128x128, 8 warps (2x4), warp tile 64x32, BK=32, 2 smem stages.
// Smem b32 row stride 20 -> fragment LDS conflict-free (20g mod 32 spans
// all multiples of 4; +qid covers all 32 banks).
// ---------------------------------------------------------------------------
#define KSTR 20                 // b32 per smem row (16 data + 4 pad)
#define STGU (128 * KSTR)       // u32 per array per stage

__device__ __forceinline__ uint32_t smem_u32(const void* p) {
    uint32_t a;
    asm("{ .reg .u64 t; cvta.to.shared.u64 t, %1; cvt.u32.u64 %0, t; }"
        : "=r"(a) : "l"(p));
    return a;
}
#define CPA16(dst, src) \
    asm volatile("cp.async.cg.shared.global [%0], [%1], 16;" \
                 :: "r"(dst), "l"(src))

__device__ __forceinline__ void mma_bf16(float d[4], const uint32_t a[4],
                                         const uint32_t b[2]) {
    asm volatile(
        "mma.sync.aligned.m16n8k16.row.col.f32.bf16.bf16.f32 "
        "{%0,%1,%2,%3}, {%4,%5,%6,%7}, {%8,%9}, {%0,%1,%2,%3};\n"
        : "+f"(d[0]), "+f"(d[1]), "+f"(d[2]), "+f"(d[3])
        : "r"(a[0]), "r"(a[1]), "r"(a[2]), "r"(a[3]), "r"(b[0]), "r"(b[1]));
}

template <int MODE>
__global__ __launch_bounds__(256)
void gemm_bf16(const float* __restrict__ bias, float* __restrict__ Cout,
               int M, int N, int K)
{
    const __nv_bfloat16* __restrict__ Ah = (MODE == 0) ? g_xh : g_yh;
    const __nv_bfloat16* __restrict__ Al = (MODE == 0) ? g_xl : g_yl;
    const __nv_bfloat16* __restrict__ Bh = (MODE == 0) ? g_wqh : g_wph;
    const __nv_bfloat16* __restrict__ Bl = (MODE == 0) ? g_wql : g_wpl;
    float* __restrict__ C = (MODE == 0) ? g_qkv : Cout;

    extern __shared__ uint32_t sg[];          // [2 stages][4 arrays][STGU]
    const uint32_t sb = smem_u32(sg);

    const int tid  = threadIdx.x;
    const int warp = tid >> 5;
    const int lane = tid & 31;
    const int grp  = lane >> 2;
    const int qid  = lane & 3;
    const int wy   = warp >> 2;               // 0..1
    const int wx   = warp & 3;                // 0..3
    const int brow = blockIdx.y * 128;
    const int bcol = blockIdx.x * 128;

    float Cacc[4][4][4];
#pragma unroll
    for (int mt = 0; mt < 4; mt++)
#pragma unroll
        for (int nt = 0; nt < 4; nt++)
#pragma unroll
            for (int c = 0; c < 4; c++) Cacc[mt][nt][c] = 0.0f;

    const int ldrow = tid >> 2;               // pairs with it: 2 its x 256
    const int ldu   = tid & 3;

    const int nsteps = K >> 5;                // 24

    // ---- stage loader (cp.async) ----
    auto load_stage = [&](int s, int kofs) {
#pragma unroll
        for (int it = 0; it < 2; it++) {
            const int row = ldrow + it * 64;          // 0..127
            const int u   = ldu;                      // 16B unit 0..3
            const size_t ga = (size_t)(brow + row) * K + kofs + u * 8;
            const size_t gb = (size_t)(bcol + row) * K + kofs + u * 8;
            const uint32_t off = (uint32_t)(row * KSTR + u * 4) * 4;
            CPA16(sb + ((s * 4 + 0) * STGU) * 4 + off, Ah + ga);
            CPA16(sb + ((s * 4 + 1) * STGU) * 4 + off, Al + ga);
            CPA16(sb + ((s * 4 + 2) * STGU) * 4 + off, Bh + gb);
            CPA16(sb + ((s * 4 + 3) * STGU) * 4 + off, Bl + gb);
        }
        asm volatile("cp.async.commit_group;");
    };

    load_stage(0, 0);

    for (int step = 0; step < nsteps; step++) {
        const int s = step & 1;
        const bool pref = (step + 1 < nsteps);
        if (pref) load_stage(s ^ 1, (step + 1) << 5);
        if (pref) asm volatile("cp.async.wait_group 1;");
        else      asm volatile("cp.async.wait_group 0;");
        __syncthreads();

        const uint32_t* sAh = sg + (s * 4 + 0) * STGU;
        const uint32_t* sAl = sg + (s * 4 + 1) * STGU;
        const uint32_t* sBh = sg + (s * 4 + 2) * STGU;
        const uint32_t* sBl = sg + (s * 4 + 3) * STGU;

#pragma unroll
        for (int kk = 0; kk < 2; kk++) {       // 2 x k16
            const int kb = kk * 8;
            uint32_t bh[4][2], bl[4][2];
#pragma unroll
            for (int nt = 0; nt < 4; nt++) {
                const int n = wx * 32 + nt * 8 + grp;
                bh[nt][0] = sBh[n * KSTR + kb + qid];
                bh[nt][1] = sBh[n * KSTR + kb + 4 + qid];
                bl[nt][0] = sBl[n * KSTR + kb + qid];
                bl[nt][1] = sBl[n * KSTR + kb + 4 + qid];
            }
#pragma unroll
            for (int mt = 0; mt < 4; mt++) {
                const int r0 = wy * 64 + mt * 16 + grp;
                uint32_t ah[4], al[4];
                ah[0] = sAh[r0 * KSTR + kb + qid];
                ah[1] = sAh[(r0 + 8) * KSTR + kb + qid];
                ah[2] = sAh[r0 * KSTR + kb + 4 + qid];
                ah[3] = sAh[(r0 + 8) * KSTR + kb + 4 + qid];
                al[0] = sAl[r0 * KSTR + kb + qid];
                al[1] = sAl[(r0 + 8) * KSTR + kb + qid];
                al[2] = sAl[r0 * KSTR + kb + 4 + qid];
                al[3] = sAl[(r0 + 8) * KSTR + kb + 4 + qid];
#pragma unroll
                for (int nt = 0; nt < 4; nt++) {
                    mma_bf16(Cacc[mt][nt], ah, bh[nt]);
                    mma_bf16(Cacc[mt][nt], ah, bl[nt]);
                    mma_bf16(Cacc[mt][nt], al, bh[nt]);
                }
            }
        }
        __syncthreads();   // all reads of stage s done before it is refilled
    }

    // Epilogue: bias + store fp32
#pragma unroll
    for (int mt = 0; mt < 4; mt++) {
        const int r0 = brow + wy * 64 + mt * 16 + grp;
#pragma unroll
        for (int nt = 0; nt < 4; nt++) {
            const int cc = bcol + wx * 32 + nt * 8 + 2 * qid;
            const float b0 = bias[cc], b1 = bias[cc + 1];
            float2 o0 = make_float2(Cacc[mt][nt][0] + b0, Cacc[mt][nt][1] + b1);
            float2 o1 = make_float2(Cacc[mt][nt][2] + b0, Cacc[mt][nt][3] + b1);
            *reinterpret_cast<float2*>(&C[(size_t)r0 * N + cc])       = o0;
            *reinterpret_cast<float2*>(&C[(size_t)(r0 + 8) * N + cc]) = o1;
        }
    }
}

// ----------------------------------------------------------------------------
// Causal flash attention (tf32 mma.sync.m16n8k8), 128-row q-tiles.
// 256 threads = 8 warps x 16 q-rows; K/V tiles stay 64 rows -> halves the
// L2 re-read traffic of K/V vs 64-row q-tiles.
// ----------------------------------------------------------------------------
#define QK_STRIDE 68
#define V_STRIDE  72

__device__ __forceinline__ float ftf32(float x) {
    asm("cvt.rna.tf32.f32 %0, %0;" : "+f"(x));
    return x;
}
__device__ __forceinline__ float ex2f_fast(float x) {
    float y; asm("ex2.approx.f32 %0, %1;" : "=f"(y) : "f"(x)); return y;
}
__device__ __forceinline__ void mma_tf32(float d[4], const unsigned a[4], const unsigned b[2]) {
    asm volatile(
        "mma.sync.aligned.m16n8k8.row.col.f32.tf32.tf32.f32 "
        "{%0,%1,%2,%3}, {%4,%5,%6,%7}, {%8,%9}, {%0,%1,%2,%3};\n"
        : "+f"(d[0]), "+f"(d[1]), "+f"(d[2]), "+f"(d[3])
        : "r"(a[0]), "r"(a[1]), "r"(a[2]), "r"(a[3]), "r"(b[0]), "r"(b[1]));
}

__global__ __launch_bounds__(256)
void flash_attn_tf32()
{
    extern __shared__ float sm[];
    float* Qs = sm;                        // [128][68]
    float* Ks = Qs + 128 * QK_STRIDE;      // [64][68]
    float* Vs = Ks + 64 * QK_STRIDE;       // [64][72]
    float* Ps = Vs + 64 * V_STRIDE;        // [128][68]

    const int h     = blockIdx.y;
    const int qtile = gridDim.x - 1 - blockIdx.x;   // heavy tiles first
    const int q0    = qtile * 128;
    const int tid   = threadIdx.x;
    const int warp  = tid >> 5;            // 0..7
    const int lane  = tid & 31;
    const int grp   = lane >> 2;
    const int qid   = lane & 3;
    const int i0    = warp * 16;           // 0..112

    const float QSCALE = 0.125f * 1.4426950408889634f;
    for (int it = 0; it < 8; it++) {
        const int idx = it * 256 + tid;
        const int row = idx >> 4;          // 0..127
        const int c4  = (idx & 15) << 2;
        float4 v = *reinterpret_cast<const float4*>(
            &g_qkv[(size_t)(q0 + row) * QKVN + h * DHEAD + c4]);
        v.x = ftf32(v.x * QSCALE); v.y = ftf32(v.y * QSCALE);
        v.z = ftf32(v.z * QSCALE); v.w = ftf32(v.w * QSCALE);
        *reinterpret_cast<float4*>(&Qs[row * QK_STRIDE + c4]) = v;
    }

    float O[8][4];
#pragma unroll
    for (int dt = 0; dt < 8; dt++)
#pragma unroll
        for (int c = 0; c < 4; c++) O[dt][c] = 0.0f;
    float m0 = -1e30f, m1 = -1e30f, l0 = 0.0f, l1 = 0.0f;

    const unsigned* Qu = reinterpret_cast<const unsigned*>(Qs);
    const unsigned* Ku = reinterpret_cast<const unsigned*>(Ks);
    const unsigned* Vu = reinterpret_cast<const unsigned*>(Vs);
    const unsigned* Pu = reinterpret_cast<const unsigned*>(Ps);

    const int nk = 2 * qtile + 2;
    for (int kt = 0; kt < nk; kt++) {
        const int k0 = kt * 64;
        __syncthreads();
        for (int it = 0; it < 4; it++) {
            const int idx = it * 256 + tid;
            const int row = idx >> 4;      // 0..63
            const int c4  = (idx & 15) << 2;
            const float* bp = &g_qkv[(size_t)(k0 + row) * QKVN + h * DHEAD + c4];
            float4 kv = *reinterpret_cast<const float4*>(bp + CDIM);
            float4 vv = *reinterpret_cast<const float4*>(bp + 2 * CDIM);
            kv.x = ftf32(kv.x); kv.y = ftf32(kv.y); kv.z = ftf32(kv.z); kv.w = ftf32(kv.w);
            vv.x = ftf32(vv.x); vv.y = ftf32(vv.y); vv.z = ftf32(vv.z); vv.w = ftf32(vv.w);
            *reinterpret_cast<float4*>(&Ks[row * QK_STRIDE + c4]) = kv;
            *reinterpret_cast<float4*>(&Vs[row * V_STRIDE  + c4]) = vv;
        }
        __syncthreads();

        float S[8][4];
#pragma unroll
        for (int nt = 0; nt < 8; nt++)
#pragma unroll
            for (int c = 0; c < 4; c++) S[nt][c] = 0.0f;

#pragma unroll
        for (int kk = 0; kk < 8; kk++) {
            unsigned a[4];
            const int ai = (i0 + grp) * QK_STRIDE + kk * 8 + qid;
            a[0] = Qu[ai];
            a[1] = Qu[ai + 8 * QK_STRIDE];
            a[2] = Qu[ai + 4];
            a[3] = Qu[ai + 8 * QK_STRIDE + 4];
#pragma unroll
            for (int nt = 0; nt < 8; nt++) {
                unsigned b[2];
                const int bi = (nt * 8 + grp) * QK_STRIDE + kk * 8 + qid;
                b[0] = Ku[bi];
                b[1] = Ku[bi + 4];
                mma_tf32(S[nt], a, b);
            }
        }

        const int r0 = i0 + grp;           // local q row (0..127)
        const int r1 = r0 + 8;
        if (kt >= nk - 2) {                // diagonal band tiles
            const int joff = k0 - q0;      // 0 or 64
#pragma unroll
            for (int nt = 0; nt < 8; nt++) {
                const int jb = joff + nt * 8 + 2 * qid;
                if (jb     > r0) S[nt][0] = -1e30f;
                if (jb + 1 > r0) S[nt][1] = -1e30f;
                if (jb     > r1) S[nt][2] = -1e30f;
                if (jb + 1 > r1) S[nt][3] = -1e30f;
            }
        }

        float mx0 = -1e30f, mx1 = -1e30f;
#pragma unroll
        for (int nt = 0; nt < 8; nt++) {
            mx0 = fmaxf(mx0, fmaxf(S[nt][0], S[nt][1]));
            mx1 = fmaxf(mx1, fmaxf(S[nt][2], S[nt][3]));
        }
        mx0 = fmaxf(mx0, __shfl_xor_sync(0xffffffffu, mx0, 1));
        mx0 = fmaxf(mx0, __shfl_xor_sync(0xffffffffu, mx0, 2));
        mx1 = fmaxf(mx1, __shfl_xor_sync(0xffffffffu, mx1, 1));
        mx1 = fmaxf(mx1, __shfl_xor_sync(0xffffffffu, mx1, 2));

        const float mn0 = fmaxf(m0, mx0);
        const float mn1 = fmaxf(m1, mx1);
        const float al0 = ex2f_fast(m0 - mn0);
        const float al1 = ex2f_fast(m1 - mn1);
        m0 = mn0; m1 = mn1;

        float rs0 = 0.0f, rs1 = 0.0f;
#pragma unroll
        for (int nt = 0; nt < 8; nt++) {
            S[nt][0] = ex2f_fast(S[nt][0] - mn0); rs0 += S[nt][0];
            S[nt][1] = ex2f_fast(S[nt][1] - mn0); rs0 += S[nt][1];
            S[nt][2] = ex2f_fast(S[nt][2] - mn1); rs1 += S[nt][2];
            S[nt][3] = ex2f_fast(S[nt][3] - mn1); rs1 += S[nt][3];
        }
        rs0 += __shfl_xor_sync(0xffffffffu, rs0, 1);
        rs0 += __shfl_xor_sync(0xffffffffu, rs0, 2);
        rs1 += __shfl_xor_sync(0xffffffffu, rs1, 1);
        rs1 += __shfl_xor_sync(0xffffffffu, rs1, 2);
        l0 = l0 * al0 + rs0;
        l1 = l1 * al1 + rs1;

#pragma unroll
        for (int dt = 0; dt < 8; dt++) {
            O[dt][0] *= al0; O[dt][1] *= al0;
            O[dt][2] *= al1; O[dt][3] *= al1;
        }

        {
            float* p0 = &Ps[r0 * QK_STRIDE + 2 * qid];
            float* p1 = &Ps[r1 * QK_STRIDE + 2 * qid];
#pragma unroll
            for (int nt = 0; nt < 8; nt++) {
                float2 w0 = make_float2(ftf32(S[nt][0]), ftf32(S[nt][1]));
                float2 w1 = make_float2(ftf32(S[nt][2]), ftf32(S[nt][3]));
                *reinterpret_cast<float2*>(p0 + nt * 8) = w0;
                *reinterpret_cast<float2*>(p1 + nt * 8) = w1;
            }
        }
        __syncwarp();

#pragma unroll
        for (int kk = 0; kk < 8; kk++) {
            unsigned a[4];
            const int ai = (i0 + grp) * QK_STRIDE + kk * 8 + qid;
            a[0] = Pu[ai];
            a[1] = Pu[ai + 8 * QK_STRIDE];
            a[2] = Pu[ai + 4];
            a[3] = Pu[ai + 8 * QK_STRIDE + 4];
#pragma unroll
            for (int dt = 0; dt < 8; dt++) {
                unsigned b[2];
                const int bi = (kk * 8 + qid) * V_STRIDE + dt * 8 + grp;
                b[0] = Vu[bi];
                b[1] = Vu[bi + 4 * V_STRIDE];
                mma_tf32(O[dt], a, b);
            }
        }
        __syncwarp();
    }

    // Normalize; write bf16 hi/lo pairs directly
    const float inv0 = 1.0f / l0;
    const float inv1 = 1.0f / l1;
    const int gr0 = q0 + i0 + grp;
    __nv_bfloat162* yh2 = reinterpret_cast<__nv_bfloat162*>(g_yh);
    __nv_bfloat162* yl2 = reinterpret_cast<__nv_bfloat162*>(g_yl);
#pragma unroll
    for (int dt = 0; dt < 8; dt++) {
        const int coff = h * DHEAD + dt * 8 + 2 * qid;
        const float v0 = O[dt][0] * inv0, v1 = O[dt][1] * inv0;
        const float v2 = O[dt][2] * inv1, v3 = O[dt][3] * inv1;
        const __nv_bfloat16 h0 = __float2bfloat16(v0), h1 = __float2bfloat16(v1);
        const __nv_bfloat16 h2 = __float2bfloat16(v2), h3 = __float2bfloat16(v3);
        const size_t p0 = ((size_t)gr0 * CDIM + coff) >> 1;
        const size_t p1 = ((size_t)(gr0 + 8) * CDIM + coff) >> 1;
        yh2[p0] = __nv_bfloat162(h0, h1);
        yh2[p1] = __nv_bfloat162(h2, h3);
        yl2[p0] = __nv_bfloat162(__float2bfloat16(v0 - __bfloat162float(h0)),
                                 __float2bfloat16(v1 - __bfloat162float(h1)));
        yl2[p1] = __nv_bfloat162(__float2bfloat16(v2 - __bfloat162float(h2)),
                                 __float2bfloat16(v3 - __bfloat162float(h3)));
    }
}

// ----------------------------------------------------------------------------
// Launch
// ----------------------------------------------------------------------------
extern "C" void kernel_launch(void* const* d_in, const int* in_sizes, int n_in,
                              void* d_out, int out_size)
{
    const float* x      = (const float*)d_in[0];
    const float* W_qkv  = (const float*)d_in[2];
    const float* b_qkv  = (const float*)d_in[3];
    const float* W_proj = (const float*)d_in[4];
    const float* b_proj = (const float*)d_in[5];
    float* out = (float*)d_out;

    constexpr int gemm_smem = 2 * 4 * STGU * 4;   // 81920 bytes
    cudaFuncSetAttribute(gemm_bf16<0>, cudaFuncAttributeMaxDynamicSharedMemorySize,
                         gemm_smem);
    cudaFuncSetAttribute(gemm_bf16<1>, cudaFuncAttributeMaxDynamicSharedMemorySize,
                         gemm_smem);

    // 0) Pre-convert to bf16 hi/lo
    {
        const int n4 = TSEQ * CDIM / 4;
        split_x<<<(n4 + 255) / 256, 256>>>(x, n4);
        transpose_split<0><<<dim3(QKVN / 32, CDIM / 32), dim3(32, 8)>>>(
            W_qkv, CDIM, QKVN);
        transpose_split<1><<<dim3(CDIM / 32, CDIM / 32), dim3(32, 8)>>>(
            W_proj, CDIM, CDIM);
    }

    // 1) QKV projection: [4096,768]@[768,2304]+b -> g_qkv
    {
        dim3 grid(QKVN / 128, TSEQ / 128);
        gemm_bf16<0><<<grid, 256, gemm_smem>>>(b_qkv, nullptr, TSEQ, QKVN, CDIM);
    }

    // 2) Causal flash attention (tf32), 128-row q-tiles -> g_yh/g_yl
    {
        constexpr int smem_bytes =
            (128 * QK_STRIDE + 64 * QK_STRIDE + 64 * V_STRIDE + 128 * QK_STRIDE)
            * (int)sizeof(float);   // 105472
        cudaFuncSetAttribute(flash_attn_tf32,
                             cudaFuncAttributeMaxDynamicSharedMemorySize,
                             smem_bytes);
        dim3 grid(TSEQ / 128, NHEAD);
        flash_attn_tf32<<<grid, 256, smem_bytes>>>();
    }

    // 3) Output projection: [4096,768]@[768,768]+b -> out
    {
        dim3 grid(CDIM / 128, TSEQ / 128);
        gemm_bf16<1><<<grid, 256, gemm_smem>>>(b_proj, out, TSEQ, CDIM, CDIM);
    }
}

// round 16
// speedup vs baseline: 2.5387x; 1.0006x over previous
#include <cuda_runtime.h>
#include <cuda_bf16.h>
#include <cstdint>

// Problem constants (B=1)
#define TSEQ   4096
#define CDIM   768
#define NHEAD  12
#define DHEAD  64
#define QKVN   2304   // 3*C

// ---------------------------------------------------------------------------
// Scratch (allocation-free rule: __device__ globals). Referenced ONLY from
// device code (template MODE selection).
// ---------------------------------------------------------------------------
__device__ float g_qkv[TSEQ * QKVN];   // [T, 3C]; Q pre-scaled, all tf32-rounded

__device__ __align__(16) __nv_bfloat16 g_xh[TSEQ * CDIM];
__device__ __align__(16) __nv_bfloat16 g_xl[TSEQ * CDIM];
__device__ __align__(16) __nv_bfloat16 g_yh[TSEQ * CDIM];   // attn out hi
__device__ __align__(16) __nv_bfloat16 g_yl[TSEQ * CDIM];   // attn out lo
__device__ __align__(16) __nv_bfloat16 g_wqh[QKVN * CDIM];  // W_qkv^T
__device__ __align__(16) __nv_bfloat16 g_wql[QKVN * CDIM];
__device__ __align__(16) __nv_bfloat16 g_wph[CDIM * CDIM];  // W_proj^T
__device__ __align__(16) __nv_bfloat16 g_wpl[CDIM * CDIM];

__device__ __forceinline__ float ftf32(float x) {
    asm("cvt.rna.tf32.f32 %0, %0;" : "+f"(x));
    return x;
}

// ---------------------------------------------------------------------------
// fp32 -> bf16 hi/lo split of x
// ---------------------------------------------------------------------------
__global__ void split_x(const float* __restrict__ in, int n4)
{
    __nv_bfloat16* __restrict__ oh = g_xh;
    __nv_bfloat16* __restrict__ ol = g_xl;
    const int i = blockIdx.x * blockDim.x + threadIdx.x;
    if (i >= n4) return;
    const float4 v = reinterpret_cast<const float4*>(in)[i];
    __nv_bfloat16 h0 = __float2bfloat16(v.x), h1 = __float2bfloat16(v.y);
    __nv_bfloat16 h2 = __float2bfloat16(v.z), h3 = __float2bfloat16(v.w);
    reinterpret_cast<__nv_bfloat162*>(oh)[2 * i]     = __nv_bfloat162(h0, h1);
    reinterpret_cast<__nv_bfloat162*>(oh)[2 * i + 1] = __nv_bfloat162(h2, h3);
    reinterpret_cast<__nv_bfloat162*>(ol)[2 * i] =
        __nv_bfloat162(__float2bfloat16(v.x - __bfloat162float(h0)),
                       __float2bfloat16(v.y - __bfloat162float(h1)));
    reinterpret_cast<__nv_bfloat162*>(ol)[2 * i + 1] =
        __nv_bfloat162(__float2bfloat16(v.z - __bfloat162float(h2)),
                       __float2bfloat16(v.w - __bfloat162float(h3)));
}

// W [K][N] fp32 -> [N][K] bf16 hi/lo (transpose + split).
template <int MODE>
__global__ void transpose_split(const float* __restrict__ W, int K, int N)
{
    __nv_bfloat16* __restrict__ oh = (MODE == 0) ? g_wqh : g_wph;
    __nv_bfloat16* __restrict__ ol = (MODE == 0) ? g_wql : g_wpl;
    __shared__ float t[32][33];
    const int nx = blockIdx.x * 32, ky = blockIdx.y * 32;
    const int txx = threadIdx.x, tyy = threadIdx.y;
#pragma unroll
    for (int j = 0; j < 32; j += 8)
        t[tyy + j][txx] = W[(size_t)(ky + tyy + j) * N + nx + txx];
    __syncthreads();
#pragma unroll
    for (int j = 0; j < 32; j += 8) {
        const float v = t[txx][tyy + j];
        const __nv_bfloat16 h = __float2bfloat16(v);
        oh[(size_t)(nx + tyy + j) * K + ky + txx] = h;
        ol[(size_t)(nx + tyy + j) * K + ky + txx] =
            __float2bfloat16(v - __bfloat162float(h));
    }
}

// ---------------------------------------------------------------------------
// bf16 split GEMM, cp.async double-buffered, 2 CTAs/SM (regs capped at 128):
//   C = Ah*Bh + Ah*Bl + Al*Bh + bias
// MODE 0 epilogue additionally pre-bakes attention input format into g_qkv:
//   cols <  768 (Q):  out = tf32(  (acc+bias) * 0.125*log2e )
//   cols >= 768 (KV): out = tf32( acc+bias )
// ---------------------------------------------------------------------------
#define KSTR 20                 // b32 per smem row (16 data + 4 pad)
#define STGU (128 * KSTR)       // u32 per array per stage

__device__ __forceinline__ uint32_t smem_u32(const void* p) {
    uint32_t a;
    asm("{ .reg .u64 t; cvta.to.shared.u64 t, %1; cvt.u32.u64 %0, t; }"
        : "=r"(a) : "l"(p));
    return a;
}
#define CPA16(dst, src) \
    asm volatile("cp.async.cg.shared.global [%0], [%1], 16;" \
                 :: "r"(dst), "l"(src))

__device__ __forceinline__ void mma_bf16(float d[4], const uint32_t a[4],
                                         const uint32_t b[2]) {
    asm volatile(
        "mma.sync.aligned.m16n8k16.row.col.f32.bf16.bf16.f32 "
        "{%0,%1,%2,%3}, {%4,%5,%6,%7}, {%8,%9}, {%0,%1,%2,%3};\n"
        : "+f"(d[0]), "+f"(d[1]), "+f"(d[2]), "+f"(d[3])
        : "r"(a[0]), "r"(a[1]), "r"(a[2]), "r"(a[3]), "r"(b[0]), "r"(b[1]));
}

template <int MODE>
__global__ __launch_bounds__(256, 2)
void gemm_bf16(const float* __restrict__ bias, float* __restrict__ Cout,
               int M, int N, int K)
{
    const __nv_bfloat16* __restrict__ Ah = (MODE == 0) ? g_xh : g_yh;
    const __nv_bfloat16* __restrict__ Al = (MODE == 0) ? g_xl : g_yl;
    const __nv_bfloat16* __restrict__ Bh = (MODE == 0) ? g_wqh : g_wph;
    const __nv_bfloat16* __restrict__ Bl = (MODE == 0) ? g_wql : g_wpl;
    float* __restrict__ C = (MODE == 0) ? g_qkv : Cout;

    extern __shared__ uint32_t sg[];          // [2 stages][4 arrays][STGU]
    const uint32_t sb = smem_u32(sg);

    const int tid  = threadIdx.x;
    const int warp = tid >> 5;
    const int lane = tid & 31;
    const int grp  = lane >> 2;
    const int qid  = lane & 3;
    const int wy   = warp >> 2;               // 0..1
    const int wx   = warp & 3;                // 0..3
    const int brow = blockIdx.y * 128;
    const int bcol = blockIdx.x * 128;

    float Cacc[4][4][4];
#pragma unroll
    for (int mt = 0; mt < 4; mt++)
#pragma unroll
        for (int nt = 0; nt < 4; nt++)
#pragma unroll
            for (int c = 0; c < 4; c++) Cacc[mt][nt][c] = 0.0f;

    const int ldrow = tid >> 2;
    const int ldu   = tid & 3;

    const int nsteps = K >> 5;                // 24

    auto load_stage = [&](int s, int kofs) {
#pragma unroll
        for (int it = 0; it < 2; it++) {
            const int row = ldrow + it * 64;
            const int u   = ldu;
            const size_t ga = (size_t)(brow + row) * K + kofs + u * 8;
            const size_t gb = (size_t)(bcol + row) * K + kofs + u * 8;
            const uint32_t off = (uint32_t)(row * KSTR + u * 4) * 4;
            CPA16(sb + ((s * 4 + 0) * STGU) * 4 + off, Ah + ga);
            CPA16(sb + ((s * 4 + 1) * STGU) * 4 + off, Al + ga);
            CPA16(sb + ((s * 4 + 2) * STGU) * 4 + off, Bh + gb);
            CPA16(sb + ((s * 4 + 3) * STGU) * 4 + off, Bl + gb);
        }
        asm volatile("cp.async.commit_group;");
    };

    load_stage(0, 0);

    for (int step = 0; step < nsteps; step++) {
        const int s = step & 1;
        const bool pref = (step + 1 < nsteps);
        if (pref) load_stage(s ^ 1, (step + 1) << 5);
        if (pref) asm volatile("cp.async.wait_group 1;");
        else      asm volatile("cp.async.wait_group 0;");
        __syncthreads();

        const uint32_t* sAh = sg + (s * 4 + 0) * STGU;
        const uint32_t* sAl = sg + (s * 4 + 1) * STGU;
        const uint32_t* sBh = sg + (s * 4 + 2) * STGU;
        const uint32_t* sBl = sg + (s * 4 + 3) * STGU;

#pragma unroll
        for (int kk = 0; kk < 2; kk++) {
            const int kb = kk * 8;
            uint32_t bh[4][2], bl[4][2];
#pragma unroll
            for (int nt = 0; nt < 4; nt++) {
                const int n = wx * 32 + nt * 8 + grp;
                bh[nt][0] = sBh[n * KSTR + kb + qid];
                bh[nt][1] = sBh[n * KSTR + kb + 4 + qid];
                bl[nt][0] = sBl[n * KSTR + kb + qid];
                bl[nt][1] = sBl[n * KSTR + kb + 4 + qid];
            }
#pragma unroll
            for (int mt = 0; mt < 4; mt++) {
                const int r0 = wy * 64 + mt * 16 + grp;
                uint32_t ah[4], al[4];
                ah[0] = sAh[r0 * KSTR + kb + qid];
                ah[1] = sAh[(r0 + 8) * KSTR + kb + qid];
                ah[2] = sAh[r0 * KSTR + kb + 4 + qid];
                ah[3] = sAh[(r0 + 8) * KSTR + kb + 4 + qid];
                al[0] = sAl[r0 * KSTR + kb + qid];
                al[1] = sAl[(r0 + 8) * KSTR + kb + qid];
                al[2] = sAl[r0 * KSTR + kb + 4 + qid];
                al[3] = sAl[(r0 + 8) * KSTR + kb + 4 + qid];
#pragma unroll
                for (int nt = 0; nt < 4; nt++) {
                    mma_bf16(Cacc[mt][nt], ah, bh[nt]);
                    mma_bf16(Cacc[mt][nt], ah, bl[nt]);
                    mma_bf16(Cacc[mt][nt], al, bh[nt]);
                }
            }
        }
        __syncthreads();
    }

    // Epilogue
    const float QSCALE = 0.125f * 1.4426950408889634f;
    const bool  isQ    = (MODE == 0) && (bcol < CDIM);
#pragma unroll
    for (int mt = 0; mt < 4; mt++) {
        const int r0 = brow + wy * 64 + mt * 16 + grp;
#pragma unroll
        for (int nt = 0; nt < 4; nt++) {
            const int cc = bcol + wx * 32 + nt * 8 + 2 * qid;
            const float b0 = bias[cc], b1 = bias[cc + 1];
            float o00 = Cacc[mt][nt][0] + b0, o01 = Cacc[mt][nt][1] + b1;
            float o10 = Cacc[mt][nt][2] + b0, o11 = Cacc[mt][nt][3] + b1;
            if (MODE == 0) {
                const float sc = isQ ? QSCALE : 1.0f;
                o00 = ftf32(o00 * sc); o01 = ftf32(o01 * sc);
                o10 = ftf32(o10 * sc); o11 = ftf32(o11 * sc);
            }
            *reinterpret_cast<float2*>(&C[(size_t)r0 * N + cc]) =
                make_float2(o00, o01);
            *reinterpret_cast<float2*>(&C[(size_t)(r0 + 8) * N + cc]) =
                make_float2(o10, o11);
        }
    }
}

// ----------------------------------------------------------------------------
// Causal flash attention (tf32 mma.sync.m16n8k8), 128-row q-tiles,
// cp.async 2-stage K/V pipeline (Q/K/V pre-rounded + Q pre-scaled by gemm<0>).
// ----------------------------------------------------------------------------
#define QK_STRIDE 68
#define V_STRIDE  72
#define KSTG (64 * QK_STRIDE)   // floats per K stage
#define VSTG (64 * V_STRIDE)    // floats per V stage

__device__ __forceinline__ float ex2f_fast(float x) {
    float y; asm("ex2.approx.f32 %0, %1;" : "=f"(y) : "f"(x)); return y;
}
__device__ __forceinline__ void mma_tf32(float d[4], const unsigned a[4], const unsigned b[2]) {
    asm volatile(
        "mma.sync.aligned.m16n8k8.row.col.f32.tf32.tf32.f32 "
        "{%0,%1,%2,%3}, {%4,%5,%6,%7}, {%8,%9}, {%0,%1,%2,%3};\n"
        : "+f"(d[0]), "+f"(d[1]), "+f"(d[2]), "+f"(d[3])
        : "r"(a[0]), "r"(a[1]), "r"(a[2]), "r"(a[3]), "r"(b[0]), "r"(b[1]));
}

__global__ __launch_bounds__(256)
void flash_attn_tf32()
{
    extern __shared__ float sm[];
    float* Qs  = sm;                         // [128][68]
    float* Ks0 = Qs + 128 * QK_STRIDE;       // [2][64][68]
    float* Vs0 = Ks0 + 2 * KSTG;             // [2][64][72]
    float* Ps  = Vs0 + 2 * VSTG;             // [128][68]

    const uint32_t ksb = smem_u32(Ks0);
    const uint32_t vsb = smem_u32(Vs0);

    const int h     = blockIdx.y;
    const int qtile = gridDim.x - 1 - blockIdx.x;   // heavy tiles first
    const int q0    = qtile * 128;
    const int tid   = threadIdx.x;
    const int warp  = tid >> 5;
    const int lane  = tid & 31;
    const int grp   = lane >> 2;
    const int qid   = lane & 3;
    const int i0    = warp * 16;

    // Q tile: already scaled + tf32-rounded by gemm<0> epilogue
    for (int it = 0; it < 8; it++) {
        const int idx = it * 256 + tid;
        const int row = idx >> 4;
        const int c4  = (idx & 15) << 2;
        *reinterpret_cast<float4*>(&Qs[row * QK_STRIDE + c4]) =
            *reinterpret_cast<const float4*>(
                &g_qkv[(size_t)(q0 + row) * QKVN + h * DHEAD + c4]);
    }

    const int nk = 2 * qtile + 2;

    // K/V stage prefetch via cp.async (raw copies; data pre-rounded)
    const int prow = tid >> 2;           // 0..63
    const int pc4  = (tid & 3) << 2;     // 0,4,8,12
    auto pref = [&](int kt) {
        const int s  = kt & 1;
        const int k0 = kt * 64;
#pragma unroll
        for (int it = 0; it < 4; it++) {
            const int row = prow;
            const int c4  = pc4 + it * 16;
            const float* bp = &g_qkv[(size_t)(k0 + row) * QKVN + h * DHEAD + c4];
            CPA16(ksb + (uint32_t)(s * KSTG + row * QK_STRIDE + c4) * 4, bp + CDIM);
            CPA16(vsb + (uint32_t)(s * VSTG + row * V_STRIDE  + c4) * 4, bp + 2 * CDIM);
        }
        asm volatile("cp.async.commit_group;");
    };

    float O[8][4];
#pragma unroll
    for (int dt = 0; dt < 8; dt++)
#pragma unroll
        for (int c = 0; c < 4; c++) O[dt][c] = 0.0f;
    float m0 = -1e30f, m1 = -1e30f, l0 = 0.0f, l1 = 0.0f;

    const unsigned* Qu = reinterpret_cast<const unsigned*>(Qs);
    const unsigned* Pu = reinterpret_cast<const unsigned*>(Ps);

    pref(0);

    for (int kt = 0; kt < nk; kt++) {
        const int s = kt & 1;
        if (kt + 1 < nk) { pref(kt + 1); asm volatile("cp.async.wait_group 1;"); }
        else             { asm volatile("cp.async.wait_group 0;"); }
        __syncthreads();

        const unsigned* Ku = reinterpret_cast<const unsigned*>(Ks0 + s * KSTG);
        const unsigned* Vu = reinterpret_cast<const unsigned*>(Vs0 + s * VSTG);

        float S[8][4];
#pragma unroll
        for (int nt = 0; nt < 8; nt++)
#pragma unroll
            for (int c = 0; c < 4; c++) S[nt][c] = 0.0f;

#pragma unroll
        for (int kk = 0; kk < 8; kk++) {
            unsigned a[4];
            const int ai = (i0 + grp) * QK_STRIDE + kk * 8 + qid;
            a[0] = Qu[ai];
            a[1] = Qu[ai + 8 * QK_STRIDE];
            a[2] = Qu[ai + 4];
            a[3] = Qu[ai + 8 * QK_STRIDE + 4];
#pragma unroll
            for (int nt = 0; nt < 8; nt++) {
                unsigned b[2];
                const int bi = (nt * 8 + grp) * QK_STRIDE + kk * 8 + qid;
                b[0] = Ku[bi];
                b[1] = Ku[bi + 4];
                mma_tf32(S[nt], a, b);
            }
        }

        const int r0 = i0 + grp;
        const int r1 = r0 + 8;
        if (kt >= nk - 2) {
            const int joff = kt * 64 - q0;   // 0 or 64
#pragma unroll
            for (int nt = 0; nt < 8; nt++) {
                const int jb = joff + nt * 8 + 2 * qid;
                if (jb     > r0) S[nt][0] = -1e30f;
                if (jb + 1 > r0) S[nt][1] = -1e30f;
                if (jb     > r1) S[nt][2] = -1e30f;
                if (jb + 1 > r1) S[nt][3] = -1e30f;
            }
        }

        float mx0 = -1e30f, mx1 = -1e30f;
#pragma unroll
        for (int nt = 0; nt < 8; nt++) {
            mx0 = fmaxf(mx0, fmaxf(S[nt][0], S[nt][1]));
            mx1 = fmaxf(mx1, fmaxf(S[nt][2], S[nt][3]));
        }
        mx0 = fmaxf(mx0, __shfl_xor_sync(0xffffffffu, mx0, 1));
        mx0 = fmaxf(mx0, __shfl_xor_sync(0xffffffffu, mx0, 2));
        mx1 = fmaxf(mx1, __shfl_xor_sync(0xffffffffu, mx1, 1));
        mx1 = fmaxf(mx1, __shfl_xor_sync(0xffffffffu, mx1, 2));

        const float mn0 = fmaxf(m0, mx0);
        const float mn1 = fmaxf(m1, mx1);
        const float al0 = ex2f_fast(m0 - mn0);
        const float al1 = ex2f_fast(m1 - mn1);
        m0 = mn0; m1 = mn1;

        float rs0 = 0.0f, rs1 = 0.0f;
#pragma unroll
        for (int nt = 0; nt < 8; nt++) {
            S[nt][0] = ex2f_fast(S[nt][0] - mn0); rs0 += S[nt][0];
            S[nt][1] = ex2f_fast(S[nt][1] - mn0); rs0 += S[nt][1];
            S[nt][2] = ex2f_fast(S[nt][2] - mn1); rs1 += S[nt][2];
            S[nt][3] = ex2f_fast(S[nt][3] - mn1); rs1 += S[nt][3];
        }
        rs0 += __shfl_xor_sync(0xffffffffu, rs0, 1);
        rs0 += __shfl_xor_sync(0xffffffffu, rs0, 2);
        rs1 += __shfl_xor_sync(0xffffffffu, rs1, 1);
        rs1 += __shfl_xor_sync(0xffffffffu, rs1, 2);
        l0 = l0 * al0 + rs0;
        l1 = l1 * al1 + rs1;

#pragma unroll
        for (int dt = 0; dt < 8; dt++) {
            O[dt][0] *= al0; O[dt][1] *= al0;
            O[dt][2] *= al1; O[dt][3] *= al1;
        }

        {
            float* p0 = &Ps[r0 * QK_STRIDE + 2 * qid];
            float* p1 = &Ps[r1 * QK_STRIDE + 2 * qid];
#pragma unroll
            for (int nt = 0; nt < 8; nt++) {
                float2 w0 = make_float2(ftf32(S[nt][0]), ftf32(S[nt][1]));
                float2 w1 = make_float2(ftf32(S[nt][2]), ftf32(S[nt][3]));
                *reinterpret_cast<float2*>(p0 + nt * 8) = w0;
                *reinterpret_cast<float2*>(p1 + nt * 8) = w1;
            }
        }
        __syncwarp();

#pragma unroll
        for (int kk = 0; kk < 8; kk++) {
            unsigned a[4];
            const int ai = (i0 + grp) * QK_STRIDE + kk * 8 + qid;
            a[0] = Pu[ai];
            a[1] = Pu[ai + 8 * QK_STRIDE];
            a[2] = Pu[ai + 4];
            a[3] = Pu[ai + 8 * QK_STRIDE + 4];
#pragma unroll
            for (int dt = 0; dt < 8; dt++) {
                unsigned b[2];
                const int bi = (kk * 8 + qid) * V_STRIDE + dt * 8 + grp;
                b[0] = Vu[bi];
                b[1] = Vu[bi + 4 * V_STRIDE];
                mma_tf32(O[dt], a, b);
            }
        }
        __syncthreads();   // stage s reads done before it is refilled at kt+1
    }

    // Normalize; write bf16 hi/lo pairs directly
    const float inv0 = 1.0f / l0;
    const float inv1 = 1.0f / l1;
    const int gr0 = q0 + i0 + grp;
    __nv_bfloat162* yh2 = reinterpret_cast<__nv_bfloat162*>(g_yh);
    __nv_bfloat162* yl2 = reinterpret_cast<__nv_bfloat162*>(g_yl);
#pragma unroll
    for (int dt = 0; dt < 8; dt++) {
        const int coff = h * DHEAD + dt * 8 + 2 * qid;
        const float v0 = O[dt][0] * inv0, v1 = O[dt][1] * inv0;
        const float v2 = O[dt][2] * inv1, v3 = O[dt][3] * inv1;
        const __nv_bfloat16 h0 = __float2bfloat16(v0), h1 = __float2bfloat16(v1);
        const __nv_bfloat16 h2 = __float2bfloat16(v2), h3 = __float2bfloat16(v3);
        const size_t p0 = ((size_t)gr0 * CDIM + coff) >> 1;
        const size_t p1 = ((size_t)(gr0 + 8) * CDIM + coff) >> 1;
        yh2[p0] = __nv_bfloat162(h0, h1);
        yh2[p1] = __nv_bfloat162(h2, h3);
        yl2[p0] = __nv_bfloat162(__float2bfloat16(v0 - __bfloat162float(h0)),
                                 __float2bfloat16(v1 - __bfloat162float(h1)));
        yl2[p1] = __nv_bfloat162(__float2bfloat16(v2 - __bfloat162float(h2)),
                                 __float2bfloat16(v3 - __bfloat162float(h3)));
    }
}

// ----------------------------------------------------------------------------
// Launch
// ----------------------------------------------------------------------------
extern "C" void kernel_launch(void* const* d_in, const int* in_sizes, int n_in,
                              void* d_out, int out_size)
{
    const float* x      = (const float*)d_in[0];
    const float* W_qkv  = (const float*)d_in[2];
    const float* b_qkv  = (const float*)d_in[3];
    const float* W_proj = (const float*)d_in[4];
    const float* b_proj = (const float*)d_in[5];
    float* out = (float*)d_out;

    constexpr int gemm_smem = 2 * 4 * STGU * 4;   // 81920 bytes
    cudaFuncSetAttribute(gemm_bf16<0>, cudaFuncAttributeMaxDynamicSharedMemorySize,
                         gemm_smem);
    cudaFuncSetAttribute(gemm_bf16<1>, cudaFuncAttributeMaxDynamicSharedMemorySize,
                         gemm_smem);

    // 0) Pre-convert to bf16 hi/lo
    {
        const int n4 = TSEQ * CDIM / 4;
        split_x<<<(n4 + 255) / 256, 256>>>(x, n4);
        transpose_split<0><<<dim3(QKVN / 32, CDIM / 32), dim3(32, 8)>>>(
            W_qkv, CDIM, QKVN);
        transpose_split<1><<<dim3(CDIM / 32, CDIM / 32), dim3(32, 8)>>>(
            W_proj, CDIM, CDIM);
    }

    // 1) QKV projection -> g_qkv (Q pre-scaled, all tf32-rounded)
    {
        dim3 grid(QKVN / 128, TSEQ / 128);
        gemm_bf16<0><<<grid, 256, gemm_smem>>>(b_qkv, nullptr, TSEQ, QKVN, CDIM);
    }

    // 2) Causal flash attention (tf32, cp.async K/V pipeline) -> g_yh/g_yl
    {
        constexpr int smem_bytes =
            (128 * QK_STRIDE + 2 * KSTG + 2 * VSTG + 128 * QK_STRIDE)
            * (int)sizeof(float);   // 141312
        cudaFuncSetAttribute(flash_attn_tf32,
                             cudaFuncAttributeMaxDynamicSharedMemorySize,
                             smem_bytes);
        dim3 grid(TSEQ / 128, NHEAD);
        flash_attn_tf32<<<grid, 256, smem_bytes>>>();
    }

    // 3) Output projection -> out
    {
        dim3 grid(CDIM / 128, TSEQ / 128);
        gemm_bf16<1><<<grid, 256, gemm_smem>>>(b_proj, out, TSEQ, CDIM, CDIM);
    }
}